// round 6
// baseline (speedup 1.0000x reference)
#include <cuda_runtime.h>
#include <math.h>

#define NPTS  1024
#define D2    256
#define D3    512
#define CELLS 64
#define SBCNT 128

__device__ float g_hsum[SBCNT * CELLS * D2];
__device__ int   g_cnt [SBCNT * CELLS];

__constant__ float c_freq[8] = {
    1.0f, 1.7782794100389228f, 3.1622776601683795f, 5.623413251903491f,
    10.0f, 17.782794100389228f, 31.622776601683793f, 56.23413251903491f
};

typedef unsigned long long u64;

__device__ __forceinline__ u64 pk2(float lo, float hi) {
    u64 r; asm("mov.b64 %0,{%1,%2};" : "=l"(r) : "f"(lo), "f"(hi)); return r;
}
__device__ __forceinline__ u64 dup2(float v) { return pk2(v, v); }
__device__ __forceinline__ u64 ffma2(u64 a, u64 b, u64 c) {
    u64 d; asm("fma.rn.f32x2 %0,%1,%2,%3;" : "=l"(d) : "l"(a), "l"(b), "l"(c)); return d;
}
__device__ __forceinline__ u64 fadd2(u64 a, u64 b) {
    u64 d; asm("add.rn.f32x2 %0,%1,%2;" : "=l"(d) : "l"(a), "l"(b)); return d;
}
__device__ __forceinline__ float2 un2(u64 v) {
    float2 f; asm("mov.b64 {%0,%1},%2;" : "=f"(f.x), "=f"(f.y) : "l"(v)); return f;
}
__device__ __forceinline__ float silu_f(float v) {
    return __fdividef(v, 1.0f + __expf(-v));
}
__device__ __forceinline__ u64 silu2(u64 a) {
    float2 v = un2(a); return pk2(silu_f(v.x), silu_f(v.y));
}
// Cody-Waite mod-2pi then MUFU trig (arg reduced to [-pi,pi])
__device__ __forceinline__ float trig_red(float arg, int use_cos) {
    const float INV2PI = 0.15915494309189535f;
    const float C_HI   = 6.2831854820251465f;
    const float C_LO   = -1.7484556e-7f;
    float q = rintf(arg * INV2PI);
    float r = __fmaf_rn(-q, C_HI, arg);
    r = __fmaf_rn(-q, C_LO, r);
    return use_cos ? __cosf(r) : __sinf(r);
}

__device__ __forceinline__ unsigned smem_u32(const void* p) {
    return (unsigned)__cvta_generic_to_shared(p);
}
__device__ __forceinline__ void cpa16(unsigned s, const void* g) {
    asm volatile("cp.async.cg.shared.global [%0], [%1], 16;" :: "r"(s), "l"(g));
}

// ---------------- K1 smem layout (bytes) ----------------
#define S1_W2    0          // 131072
#define S1_W1    131072     // 16384
#define S1_ORD   147456     // 2048   (u16[1024])
#define S1_CNT   149504     // 256
#define S1_START 149760     // 272
#define S1_CUR   150032     // 256
#define SMEM1    150288

#define K1_THREADS 640
#define K1_WARPS   20
#define NBATCH     256      // 1024 points / batch-4

__global__ __launch_bounds__(K1_THREADS, 1)
void k1_embed_agg(const float* __restrict__ ds, const float* __restrict__ de,
                  const float* __restrict__ W1, const float* __restrict__ b1,
                  const float* __restrict__ W2, const float* __restrict__ b2)
{
    extern __shared__ char smem[];
    float*          W2s    = (float*)(smem + S1_W2);
    float*          W1s    = (float*)(smem + S1_W1);
    unsigned short* ordsm  = (unsigned short*)(smem + S1_ORD);
    unsigned*       cntsm  = (unsigned*)(smem + S1_CNT);
    unsigned*       startsm= (unsigned*)(smem + S1_START);
    unsigned*       cursm  = (unsigned*)(smem + S1_CUR);

    const int tid = threadIdx.x;
    const int w   = tid >> 5;
    const int l   = tid & 31;
    const int sb  = blockIdx.x;
    const int side = sb >> 6;
    const int bv   = sb & 63;
    const float* __restrict__ drags = (side ? de : ds) + (size_t)bv * NPTS * 2;
    float* gbase = g_hsum + (size_t)sb * CELLS * D2;

    // stage W2, W1; zero counters; zero this block's g_hsum slice
    {
        const float4* src2 = (const float4*)W2;
        float4* dst2 = (float4*)W2s;
        #pragma unroll 4
        for (int i = tid; i < (128 * 256) / 4; i += K1_THREADS) dst2[i] = src2[i];
        const float4* src1 = (const float4*)W1;
        float4* dst1 = (float4*)W1s;
        for (int i = tid; i < (32 * 128) / 4; i += K1_THREADS) dst1[i] = src1[i];
        float4* gz = (float4*)gbase;
        #pragma unroll 4
        for (int i = tid; i < (CELLS * D2) / 4; i += K1_THREADS)
            gz[i] = make_float4(0.f, 0.f, 0.f, 0.f);
        if (tid < 64) cntsm[tid] = 0u;
    }
    __syncthreads();

    // counting sort: pass 1
    for (int i = tid; i < NPTS; i += K1_THREADS) {
        float2 xy = *(const float2*)(drags + 2 * i);
        unsigned cell = (unsigned)((((int)xy.x) >> 6) * 8 + (((int)xy.y) >> 6));
        atomicAdd(&cntsm[cell], 1u);
    }
    __syncthreads();
    if (tid == 0) {
        unsigned run = 0;
        for (int c = 0; c < CELLS; c++) { startsm[c] = run; run += cntsm[c]; }
        startsm[CELLS] = run;
    }
    __syncthreads();
    if (tid < 64) {
        cursm[tid] = startsm[tid];
        g_cnt[sb * CELLS + tid] = (int)cntsm[tid];
    }
    __syncthreads();
    // pass 2: scatter to sorted order
    for (int i = tid; i < NPTS; i += K1_THREADS) {
        float2 xy = *(const float2*)(drags + 2 * i);
        unsigned cell = (unsigned)((((int)xy.x) >> 6) * 8 + (((int)xy.y) >> 6));
        unsigned pos = atomicAdd(&cursm[cell], 1u);
        ordsm[pos] = (unsigned short)i;
    }
    __syncthreads();

    // per-lane bias registers: lane owns cols [4l,4l+4) and [128+4l,128+4l+4)
    u64 b1r0 = *(const u64*)(b1 + 4 * l);
    u64 b1r1 = *(const u64*)(b1 + 4 * l + 2);
    u64 b2r0 = *(const u64*)(b2 + 4 * l);
    u64 b2r1 = *(const u64*)(b2 + 4 * l + 2);
    u64 b2r2 = *(const u64*)(b2 + 128 + 4 * l);
    u64 b2r3 = *(const u64*)(b2 + 128 + 4 * l + 2);

    const float fr      = c_freq[l >> 2];
    const int   use_y   = l & 1;
    const int   use_cos = (l >> 1) & 1;

    u64 run0 = 0, run1 = 0, run2 = 0, run3 = 0;
    int cur_cell = -1;

    // warp w statically claims batches w, w+20, ... of 256 batch-4's
    #pragma unroll 1
    for (int b = w; b < NBATCH; b += K1_WARPS) {
        const int p0 = 4 * b;
        float fv[4]; int cel[4];
        #pragma unroll
        for (int pp = 0; pp < 4; pp++) {
            int idx = (int)ordsm[p0 + pp];
            float2 xy = *(const float2*)(drags + 2 * idx);
            cel[pp] = (((int)xy.x) >> 6) * 8 + (((int)xy.y) >> 6);
            fv[pp] = trig_red((use_y ? xy.y : xy.x) * fr, use_cos);
        }

        // ---- L1: lane owns cols [4l, 4l+4) ----
        u64 a10 = b1r0, a11 = b1r1, a20v = b1r0, a21v = b1r1;
        u64 a30 = b1r0, a31 = b1r1, a40 = b1r0, a41 = b1r1;
        #pragma unroll 8
        for (int k = 0; k < 32; k++) {
            ulonglong2 wv = *(const ulonglong2*)(W1s + k * 128 + 4 * l);
            u64 f0 = dup2(__shfl_sync(0xffffffffu, fv[0], k));
            u64 f1 = dup2(__shfl_sync(0xffffffffu, fv[1], k));
            u64 f2 = dup2(__shfl_sync(0xffffffffu, fv[2], k));
            u64 f3 = dup2(__shfl_sync(0xffffffffu, fv[3], k));
            a10 = ffma2(f0, wv.x, a10); a11 = ffma2(f0, wv.y, a11);
            a20v = ffma2(f1, wv.x, a20v); a21v = ffma2(f1, wv.y, a21v);
            a30 = ffma2(f2, wv.x, a30); a31 = ffma2(f2, wv.y, a31);
            a40 = ffma2(f3, wv.x, a40); a41 = ffma2(f3, wv.y, a41);
        }
        // silu -> register-resident h: hu[pp][0]={cols 4l,4l+1}, [1]={4l+2,4l+3}
        u64 hu[4][2];
        hu[0][0] = silu2(a10);  hu[0][1] = silu2(a11);
        hu[1][0] = silu2(a20v); hu[1][1] = silu2(a21v);
        hu[2][0] = silu2(a30);  hu[2][1] = silu2(a31);
        hu[3][0] = silu2(a40);  hu[3][1] = silu2(a41);

        // ---- L2: h[k] fetched by warp-uniform 64-bit shfl ----
        u64 a2[4][4];
        #pragma unroll
        for (int pp = 0; pp < 4; pp++) {
            a2[pp][0] = b2r0; a2[pp][1] = b2r1;
            a2[pp][2] = b2r2; a2[pp][3] = b2r3;
        }
        #pragma unroll 2
        for (int kp = 0; kp < 64; kp++) {
            const int src = kp >> 1;
            const int sel = kp & 1;
            u64 hk[4];
            #pragma unroll
            for (int pp = 0; pp < 4; pp++)
                hk[pp] = __shfl_sync(0xffffffffu, hu[pp][sel], src);
            const float* wr0 = W2s + (2 * kp) * 256;
            ulonglong2 wA0 = *(const ulonglong2*)(wr0 + 4 * l);
            ulonglong2 wB0 = *(const ulonglong2*)(wr0 + 128 + 4 * l);
            #pragma unroll
            for (int pp = 0; pp < 4; pp++) {
                u64 h0 = dup2(un2(hk[pp]).x);
                a2[pp][0] = ffma2(h0, wA0.x, a2[pp][0]);
                a2[pp][1] = ffma2(h0, wA0.y, a2[pp][1]);
                a2[pp][2] = ffma2(h0, wB0.x, a2[pp][2]);
                a2[pp][3] = ffma2(h0, wB0.y, a2[pp][3]);
            }
            const float* wr1 = wr0 + 256;
            ulonglong2 wA1 = *(const ulonglong2*)(wr1 + 4 * l);
            ulonglong2 wB1 = *(const ulonglong2*)(wr1 + 128 + 4 * l);
            #pragma unroll
            for (int pp = 0; pp < 4; pp++) {
                u64 h1 = dup2(un2(hk[pp]).y);
                a2[pp][0] = ffma2(h1, wA1.x, a2[pp][0]);
                a2[pp][1] = ffma2(h1, wA1.y, a2[pp][1]);
                a2[pp][2] = ffma2(h1, wB1.x, a2[pp][2]);
                a2[pp][3] = ffma2(h1, wB1.y, a2[pp][3]);
            }
        }

        // ---- silu + run-accumulate; flush via RED (cross-warp safe) ----
        #pragma unroll
        for (int pp = 0; pp < 4; pp++) {
            if (cel[pp] != cur_cell) {
                if (cur_cell >= 0) {
                    float* gp = gbase + (size_t)cur_cell * D2;
                    float2 v0 = un2(run0), v1 = un2(run1);
                    float2 v2 = un2(run2), v3 = un2(run3);
                    atomicAdd(gp + 4 * l,           v0.x);
                    atomicAdd(gp + 4 * l + 1,       v0.y);
                    atomicAdd(gp + 4 * l + 2,       v1.x);
                    atomicAdd(gp + 4 * l + 3,       v1.y);
                    atomicAdd(gp + 128 + 4 * l,     v2.x);
                    atomicAdd(gp + 128 + 4 * l + 1, v2.y);
                    atomicAdd(gp + 128 + 4 * l + 2, v3.x);
                    atomicAdd(gp + 128 + 4 * l + 3, v3.y);
                }
                cur_cell = cel[pp];
                run0 = run1 = run2 = run3 = 0;
            }
            run0 = fadd2(run0, silu2(a2[pp][0]));
            run1 = fadd2(run1, silu2(a2[pp][1]));
            run2 = fadd2(run2, silu2(a2[pp][2]));
            run3 = fadd2(run3, silu2(a2[pp][3]));
        }
    }
    if (cur_cell >= 0) {
        float* gp = gbase + (size_t)cur_cell * D2;
        float2 v0 = un2(run0), v1 = un2(run1);
        float2 v2 = un2(run2), v3 = un2(run3);
        atomicAdd(gp + 4 * l,           v0.x);
        atomicAdd(gp + 4 * l + 1,       v0.y);
        atomicAdd(gp + 4 * l + 2,       v1.x);
        atomicAdd(gp + 4 * l + 3,       v1.y);
        atomicAdd(gp + 128 + 4 * l,     v2.x);
        atomicAdd(gp + 128 + 4 * l + 1, v2.y);
        atomicAdd(gp + 128 + 4 * l + 2, v3.x);
        atomicAdd(gp + 128 + 4 * l + 3, v3.y);
    }
}

// ---------------- K2 smem layout ----------------
#define S2_W3A 0        // 65536 (32 rows * 512 f)
#define S2_W3B 65536    // 65536
#define S2_HST 131072   // 66560 (256 * 65 f, padded transpose)
#define S2_B3  197632   // 2048
#define S2_CNT 199680   // 256
#define SMEM2  199936

// out = Hsum @ W3 + cnt*b3. Warp w owns cols [32w,32w+32); lane l owns
// cells l, l+32. W3 double-buffered via cp.async (8 tiles of 32 rows).
__global__ __launch_bounds__(512, 1)
void k2_l3(const float* __restrict__ W3, const float* __restrict__ b3,
           float* __restrict__ out)
{
    extern __shared__ char smem[];
    float* w3a  = (float*)(smem + S2_W3A);
    float* w3b  = (float*)(smem + S2_W3B);
    float* Hst  = (float*)(smem + S2_HST);
    float* b3s  = (float*)(smem + S2_B3);
    float* cnts = (float*)(smem + S2_CNT);

    const int tid = threadIdx.x;
    const int w   = tid >> 5;
    const int l   = tid & 31;
    const int sb  = blockIdx.x;
    const int side = sb >> 6;
    const int bv   = sb & 63;

    const unsigned sa = smem_u32(w3a);
    const unsigned sbuf[2] = { sa, sa + 65536u };

    // prefetch tile 0
    {
        const char* g0 = (const char*)W3;
        #pragma unroll
        for (int j = 0; j < 8; j++) {
            int f4 = tid + j * 512;
            cpa16(sbuf[0] + f4 * 16, g0 + (size_t)f4 * 16);
        }
        asm volatile("cp.async.commit_group;");
    }

    // stage transposed H: Hst[k*65 + cell] = g_hsum[sb][cell][k]
    {
        const float* src = g_hsum + (size_t)sb * CELLS * D2;
        for (int base = tid; base < CELLS * D2; base += 512) {
            int cell = base >> 8;
            int k    = base & 255;
            Hst[k * 65 + cell] = src[base];
        }
        b3s[tid] = b3[tid];
        if (tid < 64) cnts[tid] = (float)g_cnt[sb * CELLS + tid];
    }

    u64 acc[2][16];
    #pragma unroll
    for (int h = 0; h < 2; h++)
        #pragma unroll
        for (int j = 0; j < 16; j++) acc[h][j] = 0ull;

    #pragma unroll 1
    for (int kt = 0; kt < 8; kt++) {
        if (kt < 7) {   // prefetch next tile into other buffer
            const char* gn = (const char*)(W3 + (size_t)(kt + 1) * 32 * D3);
            #pragma unroll
            for (int j = 0; j < 8; j++) {
                int f4 = tid + j * 512;
                cpa16(sbuf[(kt + 1) & 1] + f4 * 16, gn + (size_t)f4 * 16);
            }
            asm volatile("cp.async.commit_group;");
            asm volatile("cp.async.wait_group 1;");
        } else {
            asm volatile("cp.async.wait_group 0;");
        }
        __syncthreads();

        const float* wt = (kt & 1) ? w3b : w3a;
        #pragma unroll 2
        for (int kk = 0; kk < 32; kk++) {
            const int k = kt * 32 + kk;
            u64 hd0 = dup2(Hst[k * 65 + l]);
            u64 hd1 = dup2(Hst[k * 65 + l + 32]);
            const float* wr = wt + kk * D3 + 32 * w;
            #pragma unroll
            for (int j2 = 0; j2 < 8; j2++) {   // broadcast LDS.128
                ulonglong2 wv = *(const ulonglong2*)(wr + 4 * j2);
                acc[0][2 * j2]     = ffma2(hd0, wv.x, acc[0][2 * j2]);
                acc[0][2 * j2 + 1] = ffma2(hd0, wv.y, acc[0][2 * j2 + 1]);
                acc[1][2 * j2]     = ffma2(hd1, wv.x, acc[1][2 * j2]);
                acc[1][2 * j2 + 1] = ffma2(hd1, wv.y, acc[1][2 * j2 + 1]);
            }
        }
        __syncthreads();   // protect buffer before next-next prefetch
    }

    const float c0 = cnts[l], c1 = cnts[l + 32];
    float* outp = out + ((size_t)(bv * 1024 + side * 512)) * 64;
    #pragma unroll
    for (int j = 0; j < 16; j++) {
        int col = 32 * w + 2 * j;
        float bx = b3s[col], by = b3s[col + 1];
        float2 v0 = un2(acc[0][j]);
        float2 v1 = un2(acc[1][j]);
        outp[(size_t)col       * 64 + l]      = v0.x + c0 * bx;
        outp[(size_t)(col + 1) * 64 + l]      = v0.y + c0 * by;
        outp[(size_t)col       * 64 + l + 32] = v1.x + c1 * bx;
        outp[(size_t)(col + 1) * 64 + l + 32] = v1.y + c1 * by;
    }
}

extern "C" void kernel_launch(void* const* d_in, const int* in_sizes, int n_in,
                              void* d_out, int out_size)
{
    const float* ds = (const float*)d_in[0];
    const float* de = (const float*)d_in[1];
    const float* W1 = (const float*)d_in[2];
    const float* b1 = (const float*)d_in[3];
    const float* W2 = (const float*)d_in[4];
    const float* b2 = (const float*)d_in[5];
    const float* W3 = (const float*)d_in[6];
    const float* b3 = (const float*)d_in[7];
    float* out = (float*)d_out;

    cudaFuncSetAttribute(k1_embed_agg, cudaFuncAttributeMaxDynamicSharedMemorySize, SMEM1);
    cudaFuncSetAttribute(k2_l3,        cudaFuncAttributeMaxDynamicSharedMemorySize, SMEM2);

    k1_embed_agg<<<SBCNT, K1_THREADS, SMEM1>>>(ds, de, W1, b1, W2, b2);
    k2_l3<<<SBCNT, 512, SMEM2>>>(W3, b3, out);
}

// round 7
// speedup vs baseline: 1.0448x; 1.0448x over previous
#include <cuda_runtime.h>
#include <math.h>

#define NPTS  1024
#define D2    256
#define D3    512
#define CELLS 64
#define SBCNT 128

__device__ float g_hsum[SBCNT * CELLS * D2];
__device__ int   g_cnt [SBCNT * CELLS];

__constant__ float c_freq[8] = {
    1.0f, 1.7782794100389228f, 3.1622776601683795f, 5.623413251903491f,
    10.0f, 17.782794100389228f, 31.622776601683793f, 56.23413251903491f
};

typedef unsigned long long u64;

__device__ __forceinline__ u64 pk2(float lo, float hi) {
    u64 r; asm("mov.b64 %0,{%1,%2};" : "=l"(r) : "f"(lo), "f"(hi)); return r;
}
__device__ __forceinline__ u64 dup2(float v) { return pk2(v, v); }
__device__ __forceinline__ u64 ffma2(u64 a, u64 b, u64 c) {
    u64 d; asm("fma.rn.f32x2 %0,%1,%2,%3;" : "=l"(d) : "l"(a), "l"(b), "l"(c)); return d;
}
__device__ __forceinline__ u64 fadd2(u64 a, u64 b) {
    u64 d; asm("add.rn.f32x2 %0,%1,%2;" : "=l"(d) : "l"(a), "l"(b)); return d;
}
__device__ __forceinline__ float2 un2(u64 v) {
    float2 f; asm("mov.b64 {%0,%1},%2;" : "=f"(f.x), "=f"(f.y) : "l"(v)); return f;
}
__device__ __forceinline__ float silu_f(float v) {
    return __fdividef(v, 1.0f + __expf(-v));
}
__device__ __forceinline__ u64 silu2(u64 a) {
    float2 v = un2(a); return pk2(silu_f(v.x), silu_f(v.y));
}
// Cody-Waite mod-2pi then MUFU trig (arg reduced to [-pi,pi])
__device__ __forceinline__ float trig_red(float arg, int use_cos) {
    const float INV2PI = 0.15915494309189535f;
    const float C_HI   = 6.2831854820251465f;
    const float C_LO   = -1.7484556e-7f;
    float q = rintf(arg * INV2PI);
    float r = __fmaf_rn(-q, C_HI, arg);
    r = __fmaf_rn(-q, C_LO, r);
    return use_cos ? __cosf(r) : __sinf(r);
}

__device__ __forceinline__ unsigned smem_u32(const void* p) {
    return (unsigned)__cvta_generic_to_shared(p);
}
__device__ __forceinline__ void cpa16(unsigned s, const void* g) {
    asm volatile("cp.async.cg.shared.global [%0], [%1], 16;" :: "r"(s), "l"(g));
}

// ---------------- K1 smem layout (bytes) ----------------
#define S1_W2    0          // 131072
#define S1_W1    131072     // 16384
#define S1_H1    147456     // 65536  (16 warps * 8 pts * 128 f)
#define S1_ORD   212992     // 2048   (u16[1024])
#define S1_CNT   215040     // 256
#define S1_START 215296     // 272
#define S1_CUR   215568     // 256
#define SMEM1    215824

__global__ __launch_bounds__(512, 1)
void k1_embed_agg(const float* __restrict__ ds, const float* __restrict__ de,
                  const float* __restrict__ W1, const float* __restrict__ b1,
                  const float* __restrict__ W2, const float* __restrict__ b2)
{
    extern __shared__ char smem[];
    float*          W2s    = (float*)(smem + S1_W2);
    float*          W1s    = (float*)(smem + S1_W1);
    float*          h1s    = (float*)(smem + S1_H1);
    unsigned short* ordsm  = (unsigned short*)(smem + S1_ORD);
    unsigned*       cntsm  = (unsigned*)(smem + S1_CNT);
    unsigned*       startsm= (unsigned*)(smem + S1_START);
    unsigned*       cursm  = (unsigned*)(smem + S1_CUR);

    const int tid = threadIdx.x;
    const int w   = tid >> 5;
    const int l   = tid & 31;
    const int sb  = blockIdx.x;
    const int side = sb >> 6;
    const int bv   = sb & 63;
    const float* __restrict__ drags = (side ? de : ds) + (size_t)bv * NPTS * 2;
    float* gbase = g_hsum + (size_t)sb * CELLS * D2;

    // stage W2, W1; zero counters; zero this block's g_hsum slice
    {
        const float4* src2 = (const float4*)W2;
        float4* dst2 = (float4*)W2s;
        #pragma unroll 4
        for (int i = tid; i < (128 * 256) / 4; i += 512) dst2[i] = src2[i];
        const float4* src1 = (const float4*)W1;
        float4* dst1 = (float4*)W1s;
        #pragma unroll
        for (int i = tid; i < (32 * 128) / 4; i += 512) dst1[i] = src1[i];
        float4* gz = (float4*)gbase;
        #pragma unroll
        for (int i = tid; i < (CELLS * D2) / 4; i += 512)
            gz[i] = make_float4(0.f, 0.f, 0.f, 0.f);
        if (tid < 64) cntsm[tid] = 0u;
    }
    __syncthreads();

    // counting sort: pass 1
    #pragma unroll
    for (int i = tid; i < NPTS; i += 512) {
        float2 xy = *(const float2*)(drags + 2 * i);
        unsigned cell = (unsigned)((((int)xy.x) >> 6) * 8 + (((int)xy.y) >> 6));
        atomicAdd(&cntsm[cell], 1u);
    }
    __syncthreads();
    if (tid == 0) {
        unsigned run = 0;
        for (int c = 0; c < CELLS; c++) { startsm[c] = run; run += cntsm[c]; }
        startsm[CELLS] = run;
    }
    __syncthreads();
    if (tid < 64) {
        cursm[tid] = startsm[tid];
        g_cnt[sb * CELLS + tid] = (int)cntsm[tid];
    }
    __syncthreads();
    // pass 2: scatter to sorted order
    #pragma unroll
    for (int i = tid; i < NPTS; i += 512) {
        float2 xy = *(const float2*)(drags + 2 * i);
        unsigned cell = (unsigned)((((int)xy.x) >> 6) * 8 + (((int)xy.y) >> 6));
        unsigned pos = atomicAdd(&cursm[cell], 1u);
        ordsm[pos] = (unsigned short)i;
    }
    __syncthreads();

    // per-lane bias registers: lane owns cols [4l,4l+4) and [128+4l,128+4l+4)
    u64 b1r0 = *(const u64*)(b1 + 4 * l);
    u64 b1r1 = *(const u64*)(b1 + 4 * l + 2);
    u64 b2r[4];
    b2r[0] = *(const u64*)(b2 + 4 * l);
    b2r[1] = *(const u64*)(b2 + 4 * l + 2);
    b2r[2] = *(const u64*)(b2 + 128 + 4 * l);
    b2r[3] = *(const u64*)(b2 + 128 + 4 * l + 2);

    // perfectly balanced: warp w processes sorted points [64w, 64w+64)
    float* myh1 = h1s + w * 1024;

    const float fr      = c_freq[l >> 2];
    const int   use_y   = l & 1;
    const int   use_cos = (l >> 1) & 1;

    u64 run0 = 0, run1 = 0, run2 = 0, run3 = 0;
    int cur_cell = -1;

    #pragma unroll 1
    for (int p0 = 64 * w; p0 < 64 * w + 64; p0 += 8) {
        float fv[8]; int cel[8];
        #pragma unroll
        for (int pp = 0; pp < 8; pp++) {
            int idx = (int)ordsm[p0 + pp];
            float2 xy = *(const float2*)(drags + 2 * idx);
            cel[pp] = (((int)xy.x) >> 6) * 8 + (((int)xy.y) >> 6);
            fv[pp] = trig_red((use_y ? xy.y : xy.x) * fr, use_cos);
        }

        // ---- L1: lane owns cols [4l, 4l+4) ----
        u64 a1[8][2];
        #pragma unroll
        for (int pp = 0; pp < 8; pp++) { a1[pp][0] = b1r0; a1[pp][1] = b1r1; }
        #pragma unroll 4
        for (int k = 0; k < 32; k++) {
            ulonglong2 wv = *(const ulonglong2*)(W1s + k * 128 + 4 * l);
            #pragma unroll
            for (int pp = 0; pp < 8; pp++) {
                u64 f2 = dup2(__shfl_sync(0xffffffffu, fv[pp], k));
                a1[pp][0] = ffma2(f2, wv.x, a1[pp][0]);
                a1[pp][1] = ffma2(f2, wv.y, a1[pp][1]);
            }
        }
        #pragma unroll
        for (int pp = 0; pp < 8; pp++) {
            float2 v0 = un2(a1[pp][0]), v1 = un2(a1[pp][1]);
            float4 hv = make_float4(silu_f(v0.x), silu_f(v0.y),
                                    silu_f(v1.x), silu_f(v1.y));
            *(float4*)(myh1 + pp * 128 + 4 * l) = hv;
        }
        __syncwarp();

        // ---- L2: lane owns cols [4l,4l+4) and [128+4l,128+4l+4) ----
        u64 a2[8][4];
        #pragma unroll
        for (int pp = 0; pp < 8; pp++) {
            a2[pp][0] = b2r[0]; a2[pp][1] = b2r[1];
            a2[pp][2] = b2r[2]; a2[pp][3] = b2r[3];
        }
        #pragma unroll 2
        for (int kp = 0; kp < 64; kp++) {
            float2 hp[8];
            #pragma unroll
            for (int pp = 0; pp < 8; pp++)     // broadcast LDS.64
                hp[pp] = *(const float2*)(myh1 + pp * 128 + 2 * kp);
            #pragma unroll
            for (int s = 0; s < 2; s++) {
                const float* wr = W2s + (2 * kp + s) * 256;
                ulonglong2 wA = *(const ulonglong2*)(wr + 4 * l);
                ulonglong2 wB = *(const ulonglong2*)(wr + 128 + 4 * l);
                #pragma unroll
                for (int pp = 0; pp < 8; pp++) {
                    u64 hd = dup2(s ? hp[pp].y : hp[pp].x);
                    a2[pp][0] = ffma2(hd, wA.x, a2[pp][0]);
                    a2[pp][1] = ffma2(hd, wA.y, a2[pp][1]);
                    a2[pp][2] = ffma2(hd, wB.x, a2[pp][2]);
                    a2[pp][3] = ffma2(hd, wB.y, a2[pp][3]);
                }
            }
        }

        // ---- silu + run-accumulate; flush via RED (cross-warp cells safe) ----
        #pragma unroll
        for (int pp = 0; pp < 8; pp++) {
            if (cel[pp] != cur_cell) {
                if (cur_cell >= 0) {
                    float* gp = gbase + (size_t)cur_cell * D2;
                    float2 v0 = un2(run0), v1 = un2(run1);
                    float2 v2 = un2(run2), v3 = un2(run3);
                    atomicAdd(gp + 4 * l,           v0.x);
                    atomicAdd(gp + 4 * l + 1,       v0.y);
                    atomicAdd(gp + 4 * l + 2,       v1.x);
                    atomicAdd(gp + 4 * l + 3,       v1.y);
                    atomicAdd(gp + 128 + 4 * l,     v2.x);
                    atomicAdd(gp + 128 + 4 * l + 1, v2.y);
                    atomicAdd(gp + 128 + 4 * l + 2, v3.x);
                    atomicAdd(gp + 128 + 4 * l + 3, v3.y);
                }
                cur_cell = cel[pp];
                run0 = run1 = run2 = run3 = 0;
            }
            run0 = fadd2(run0, silu2(a2[pp][0]));
            run1 = fadd2(run1, silu2(a2[pp][1]));
            run2 = fadd2(run2, silu2(a2[pp][2]));
            run3 = fadd2(run3, silu2(a2[pp][3]));
        }
        __syncwarp();
    }
    if (cur_cell >= 0) {
        float* gp = gbase + (size_t)cur_cell * D2;
        float2 v0 = un2(run0), v1 = un2(run1);
        float2 v2 = un2(run2), v3 = un2(run3);
        atomicAdd(gp + 4 * l,           v0.x);
        atomicAdd(gp + 4 * l + 1,       v0.y);
        atomicAdd(gp + 4 * l + 2,       v1.x);
        atomicAdd(gp + 4 * l + 3,       v1.y);
        atomicAdd(gp + 128 + 4 * l,     v2.x);
        atomicAdd(gp + 128 + 4 * l + 1, v2.y);
        atomicAdd(gp + 128 + 4 * l + 2, v3.x);
        atomicAdd(gp + 128 + 4 * l + 3, v3.y);
    }
}

// ---------------- K2 smem layout ----------------
#define S2_W3A 0        // 65536 (32 rows * 512 f)
#define S2_W3B 65536    // 65536
#define S2_HST 131072   // 66560 (256 * 65 f, padded transpose)
#define S2_B3  197632   // 2048
#define S2_CNT 199680   // 256
#define SMEM2  199936

#define K2_THREADS 1024

// out = Hsum @ W3 + cnt*b3. 32 warps: warp w owns cols [16w,16w+16);
// lane l owns cells l, l+32. W3 double-buffered via cp.async (8x32-row tiles).
__global__ __launch_bounds__(K2_THREADS, 1)
void k2_l3(const float* __restrict__ W3, const float* __restrict__ b3,
           float* __restrict__ out)
{
    extern __shared__ char smem[];
    float* w3a  = (float*)(smem + S2_W3A);
    float* w3b  = (float*)(smem + S2_W3B);
    float* Hst  = (float*)(smem + S2_HST);
    float* b3s  = (float*)(smem + S2_B3);
    float* cnts = (float*)(smem + S2_CNT);

    const int tid = threadIdx.x;
    const int w   = tid >> 5;
    const int l   = tid & 31;
    const int sb  = blockIdx.x;
    const int side = sb >> 6;
    const int bv   = sb & 63;

    const unsigned sa = smem_u32(w3a);
    const unsigned sbuf[2] = { sa, sa + 65536u };

    // prefetch tile 0 (32 rows * 512 f = 4096 float4)
    {
        const char* g0 = (const char*)W3;
        #pragma unroll
        for (int j = 0; j < 4; j++) {
            int f4 = tid + j * K2_THREADS;
            cpa16(sbuf[0] + f4 * 16, g0 + (size_t)f4 * 16);
        }
        asm volatile("cp.async.commit_group;");
    }

    // stage transposed H: Hst[k*65 + cell] = g_hsum[sb][cell][k]
    {
        const float* src = g_hsum + (size_t)sb * CELLS * D2;
        #pragma unroll
        for (int base = tid; base < CELLS * D2; base += K2_THREADS) {
            int cell = base >> 8;
            int k    = base & 255;
            Hst[k * 65 + cell] = src[base];
        }
        if (tid < 512) b3s[tid] = b3[tid];
        if (tid < 64)  cnts[tid] = (float)g_cnt[sb * CELLS + tid];
    }

    u64 acc[2][8];
    #pragma unroll
    for (int h = 0; h < 2; h++)
        #pragma unroll
        for (int j = 0; j < 8; j++) acc[h][j] = 0ull;

    #pragma unroll 1
    for (int kt = 0; kt < 8; kt++) {
        if (kt < 7) {   // prefetch next tile into the other buffer
            const char* gn = (const char*)(W3 + (size_t)(kt + 1) * 32 * D3);
            #pragma unroll
            for (int j = 0; j < 4; j++) {
                int f4 = tid + j * K2_THREADS;
                cpa16(sbuf[(kt + 1) & 1] + f4 * 16, gn + (size_t)f4 * 16);
            }
            asm volatile("cp.async.commit_group;");
            asm volatile("cp.async.wait_group 1;");
        } else {
            asm volatile("cp.async.wait_group 0;");
        }
        __syncthreads();

        const float* wt = (kt & 1) ? w3b : w3a;
        #pragma unroll 2
        for (int kk = 0; kk < 32; kk++) {
            const int k = kt * 32 + kk;
            u64 hd0 = dup2(Hst[k * 65 + l]);
            u64 hd1 = dup2(Hst[k * 65 + l + 32]);
            const float* wr = wt + kk * D3 + 16 * w;
            #pragma unroll
            for (int j2 = 0; j2 < 4; j2++) {   // broadcast LDS.128
                ulonglong2 wv = *(const ulonglong2*)(wr + 4 * j2);
                acc[0][2 * j2]     = ffma2(hd0, wv.x, acc[0][2 * j2]);
                acc[0][2 * j2 + 1] = ffma2(hd0, wv.y, acc[0][2 * j2 + 1]);
                acc[1][2 * j2]     = ffma2(hd1, wv.x, acc[1][2 * j2]);
                acc[1][2 * j2 + 1] = ffma2(hd1, wv.y, acc[1][2 * j2 + 1]);
            }
        }
        __syncthreads();   // protect buffer before next prefetch overwrites
    }

    const float c0 = cnts[l], c1 = cnts[l + 32];
    float* outp = out + ((size_t)(bv * 1024 + side * 512)) * 64;
    #pragma unroll
    for (int j = 0; j < 8; j++) {
        int col = 16 * w + 2 * j;
        float bx = b3s[col], by = b3s[col + 1];
        float2 v0 = un2(acc[0][j]);
        float2 v1 = un2(acc[1][j]);
        outp[(size_t)col       * 64 + l]      = v0.x + c0 * bx;
        outp[(size_t)(col + 1) * 64 + l]      = v0.y + c0 * by;
        outp[(size_t)col       * 64 + l + 32] = v1.x + c1 * bx;
        outp[(size_t)(col + 1) * 64 + l + 32] = v1.y + c1 * by;
    }
}

extern "C" void kernel_launch(void* const* d_in, const int* in_sizes, int n_in,
                              void* d_out, int out_size)
{
    const float* ds = (const float*)d_in[0];
    const float* de = (const float*)d_in[1];
    const float* W1 = (const float*)d_in[2];
    const float* b1 = (const float*)d_in[3];
    const float* W2 = (const float*)d_in[4];
    const float* b2 = (const float*)d_in[5];
    const float* W3 = (const float*)d_in[6];
    const float* b3 = (const float*)d_in[7];
    float* out = (float*)d_out;

    cudaFuncSetAttribute(k1_embed_agg, cudaFuncAttributeMaxDynamicSharedMemorySize, SMEM1);
    cudaFuncSetAttribute(k2_l3,        cudaFuncAttributeMaxDynamicSharedMemorySize, SMEM2);

    k1_embed_agg<<<SBCNT, 512, SMEM1>>>(ds, de, W1, b1, W2, b2);
    k2_l3<<<SBCNT, K2_THREADS, SMEM2>>>(W3, b3, out);
}

// round 8
// speedup vs baseline: 1.0576x; 1.0122x over previous
#include <cuda_runtime.h>
#include <math.h>

#define NPTS  1024
#define D2    256
#define D3    512
#define CELLS 64
#define SBCNT 128

__device__ float g_hsum[SBCNT * CELLS * D2];

__constant__ float c_freq[8] = {
    1.0f, 1.7782794100389228f, 3.1622776601683795f, 5.623413251903491f,
    10.0f, 17.782794100389228f, 31.622776601683793f, 56.23413251903491f
};

typedef unsigned long long u64;

__device__ __forceinline__ u64 pk2(float lo, float hi) {
    u64 r; asm("mov.b64 %0,{%1,%2};" : "=l"(r) : "f"(lo), "f"(hi)); return r;
}
__device__ __forceinline__ u64 dup2(float v) { return pk2(v, v); }
__device__ __forceinline__ u64 ffma2(u64 a, u64 b, u64 c) {
    u64 d; asm("fma.rn.f32x2 %0,%1,%2,%3;" : "=l"(d) : "l"(a), "l"(b), "l"(c)); return d;
}
__device__ __forceinline__ u64 fadd2(u64 a, u64 b) {
    u64 d; asm("add.rn.f32x2 %0,%1,%2;" : "=l"(d) : "l"(a), "l"(b)); return d;
}
__device__ __forceinline__ float2 un2(u64 v) {
    float2 f; asm("mov.b64 {%0,%1},%2;" : "=f"(f.x), "=f"(f.y) : "l"(v)); return f;
}
__device__ __forceinline__ float silu_f(float v) {
    return __fdividef(v, 1.0f + __expf(-v));
}
__device__ __forceinline__ u64 silu2(u64 a) {
    float2 v = un2(a); return pk2(silu_f(v.x), silu_f(v.y));
}
// Cody-Waite mod-2pi then MUFU trig (arg reduced to [-pi,pi])
__device__ __forceinline__ float trig_red(float arg, int use_cos) {
    const float INV2PI = 0.15915494309189535f;
    const float C_HI   = 6.2831854820251465f;
    const float C_LO   = -1.7484556e-7f;
    float q = rintf(arg * INV2PI);
    float r = __fmaf_rn(-q, C_HI, arg);
    r = __fmaf_rn(-q, C_LO, r);
    return use_cos ? __cosf(r) : __sinf(r);
}

__device__ __forceinline__ unsigned smem_u32(const void* p) {
    return (unsigned)__cvta_generic_to_shared(p);
}
__device__ __forceinline__ void cpa16(unsigned s, const void* g) {
    asm volatile("cp.async.cg.shared.global [%0], [%1], 16;" :: "r"(s), "l"(g));
}

// ---------------- fused smem layout (bytes) ----------------
// Phase A:
#define S_W2     0          // 131072
#define S_W1     131072     // 16384
#define S_H1     147456     // 65536  (16 warps * 8 pts * 128 f)
#define S_ORD    212992     // 2048
#define S_CNT    215040     // 256   (survives into phase B)
#define S_START  215296     // 272
#define S_CUR    215568     // 256
#define SMEM_TOT 215824
// Phase B overlays (guarded by __syncthreads):
#define S_W3A    0          // 65536 (over W2s)
#define S_W3B    65536      // 65536 (over W2s)
#define S_B3     131072     // 2048  (over W1s)
#define S_HST    147456     // 66560 (over h1s + ordsm)

__global__ __launch_bounds__(512, 1)
void fused_dragnet(const float* __restrict__ ds, const float* __restrict__ de,
                   const float* __restrict__ W1, const float* __restrict__ b1,
                   const float* __restrict__ W2, const float* __restrict__ b2,
                   const float* __restrict__ W3, const float* __restrict__ b3,
                   float* __restrict__ out)
{
    extern __shared__ char smem[];
    float*          W2s    = (float*)(smem + S_W2);
    float*          W1s    = (float*)(smem + S_W1);
    float*          h1s    = (float*)(smem + S_H1);
    unsigned short* ordsm  = (unsigned short*)(smem + S_ORD);
    unsigned*       cntsm  = (unsigned*)(smem + S_CNT);
    unsigned*       startsm= (unsigned*)(smem + S_START);
    unsigned*       cursm  = (unsigned*)(smem + S_CUR);

    const int tid = threadIdx.x;
    const int w   = tid >> 5;
    const int l   = tid & 31;
    const int sb  = blockIdx.x;
    const int side = sb >> 6;
    const int bv   = sb & 63;
    const float* __restrict__ drags = (side ? de : ds) + (size_t)bv * NPTS * 2;
    float* gbase = g_hsum + (size_t)sb * CELLS * D2;

    // ================= PHASE A: embed + L1 + L2 + aggregate =================
    {
        const float4* src2 = (const float4*)W2;
        float4* dst2 = (float4*)W2s;
        #pragma unroll 4
        for (int i = tid; i < (128 * 256) / 4; i += 512) dst2[i] = src2[i];
        const float4* src1 = (const float4*)W1;
        float4* dst1 = (float4*)W1s;
        #pragma unroll
        for (int i = tid; i < (32 * 128) / 4; i += 512) dst1[i] = src1[i];
        float4* gz = (float4*)gbase;
        #pragma unroll
        for (int i = tid; i < (CELLS * D2) / 4; i += 512)
            gz[i] = make_float4(0.f, 0.f, 0.f, 0.f);
        if (tid < 64) cntsm[tid] = 0u;
    }
    __syncthreads();

    // counting sort: pass 1
    #pragma unroll
    for (int i = tid; i < NPTS; i += 512) {
        float2 xy = *(const float2*)(drags + 2 * i);
        unsigned cell = (unsigned)((((int)xy.x) >> 6) * 8 + (((int)xy.y) >> 6));
        atomicAdd(&cntsm[cell], 1u);
    }
    __syncthreads();
    if (tid == 0) {
        unsigned run = 0;
        for (int c = 0; c < CELLS; c++) { startsm[c] = run; run += cntsm[c]; }
        startsm[CELLS] = run;
    }
    __syncthreads();
    if (tid < 64) cursm[tid] = startsm[tid];
    __syncthreads();
    // pass 2: scatter to sorted order
    #pragma unroll
    for (int i = tid; i < NPTS; i += 512) {
        float2 xy = *(const float2*)(drags + 2 * i);
        unsigned cell = (unsigned)((((int)xy.x) >> 6) * 8 + (((int)xy.y) >> 6));
        unsigned pos = atomicAdd(&cursm[cell], 1u);
        ordsm[pos] = (unsigned short)i;
    }
    __syncthreads();

    {
        u64 b1r0 = *(const u64*)(b1 + 4 * l);
        u64 b1r1 = *(const u64*)(b1 + 4 * l + 2);
        u64 b2r[4];
        b2r[0] = *(const u64*)(b2 + 4 * l);
        b2r[1] = *(const u64*)(b2 + 4 * l + 2);
        b2r[2] = *(const u64*)(b2 + 128 + 4 * l);
        b2r[3] = *(const u64*)(b2 + 128 + 4 * l + 2);

        float* myh1 = h1s + w * 1024;
        const float fr      = c_freq[l >> 2];
        const int   use_y   = l & 1;
        const int   use_cos = (l >> 1) & 1;

        u64 run0 = 0, run1 = 0, run2 = 0, run3 = 0;
        int cur_cell = -1;

        #pragma unroll 1
        for (int p0 = 64 * w; p0 < 64 * w + 64; p0 += 8) {
            float fv[8]; int cel[8];
            #pragma unroll
            for (int pp = 0; pp < 8; pp++) {
                int idx = (int)ordsm[p0 + pp];
                float2 xy = *(const float2*)(drags + 2 * idx);
                cel[pp] = (((int)xy.x) >> 6) * 8 + (((int)xy.y) >> 6);
                fv[pp] = trig_red((use_y ? xy.y : xy.x) * fr, use_cos);
            }

            // L1: lane owns cols [4l, 4l+4)
            u64 a1[8][2];
            #pragma unroll
            for (int pp = 0; pp < 8; pp++) { a1[pp][0] = b1r0; a1[pp][1] = b1r1; }
            #pragma unroll 4
            for (int k = 0; k < 32; k++) {
                ulonglong2 wv = *(const ulonglong2*)(W1s + k * 128 + 4 * l);
                #pragma unroll
                for (int pp = 0; pp < 8; pp++) {
                    u64 f2 = dup2(__shfl_sync(0xffffffffu, fv[pp], k));
                    a1[pp][0] = ffma2(f2, wv.x, a1[pp][0]);
                    a1[pp][1] = ffma2(f2, wv.y, a1[pp][1]);
                }
            }
            #pragma unroll
            for (int pp = 0; pp < 8; pp++) {
                float2 v0 = un2(a1[pp][0]), v1 = un2(a1[pp][1]);
                float4 hv = make_float4(silu_f(v0.x), silu_f(v0.y),
                                        silu_f(v1.x), silu_f(v1.y));
                *(float4*)(myh1 + pp * 128 + 4 * l) = hv;
            }
            __syncwarp();

            // L2: lane owns cols [4l,4l+4) and [128+4l,128+4l+4)
            u64 a2[8][4];
            #pragma unroll
            for (int pp = 0; pp < 8; pp++) {
                a2[pp][0] = b2r[0]; a2[pp][1] = b2r[1];
                a2[pp][2] = b2r[2]; a2[pp][3] = b2r[3];
            }
            #pragma unroll 2
            for (int kp = 0; kp < 64; kp++) {
                float2 hp[8];
                #pragma unroll
                for (int pp = 0; pp < 8; pp++)
                    hp[pp] = *(const float2*)(myh1 + pp * 128 + 2 * kp);
                #pragma unroll
                for (int s = 0; s < 2; s++) {
                    const float* wr = W2s + (2 * kp + s) * 256;
                    ulonglong2 wA = *(const ulonglong2*)(wr + 4 * l);
                    ulonglong2 wB = *(const ulonglong2*)(wr + 128 + 4 * l);
                    #pragma unroll
                    for (int pp = 0; pp < 8; pp++) {
                        u64 hd = dup2(s ? hp[pp].y : hp[pp].x);
                        a2[pp][0] = ffma2(hd, wA.x, a2[pp][0]);
                        a2[pp][1] = ffma2(hd, wA.y, a2[pp][1]);
                        a2[pp][2] = ffma2(hd, wB.x, a2[pp][2]);
                        a2[pp][3] = ffma2(hd, wB.y, a2[pp][3]);
                    }
                }
            }

            // silu + run-accumulate; flush via RED (cross-warp cells safe)
            #pragma unroll
            for (int pp = 0; pp < 8; pp++) {
                if (cel[pp] != cur_cell) {
                    if (cur_cell >= 0) {
                        float* gp = gbase + (size_t)cur_cell * D2;
                        float2 v0 = un2(run0), v1 = un2(run1);
                        float2 v2 = un2(run2), v3 = un2(run3);
                        atomicAdd(gp + 4 * l,           v0.x);
                        atomicAdd(gp + 4 * l + 1,       v0.y);
                        atomicAdd(gp + 4 * l + 2,       v1.x);
                        atomicAdd(gp + 4 * l + 3,       v1.y);
                        atomicAdd(gp + 128 + 4 * l,     v2.x);
                        atomicAdd(gp + 128 + 4 * l + 1, v2.y);
                        atomicAdd(gp + 128 + 4 * l + 2, v3.x);
                        atomicAdd(gp + 128 + 4 * l + 3, v3.y);
                    }
                    cur_cell = cel[pp];
                    run0 = run1 = run2 = run3 = 0;
                }
                run0 = fadd2(run0, silu2(a2[pp][0]));
                run1 = fadd2(run1, silu2(a2[pp][1]));
                run2 = fadd2(run2, silu2(a2[pp][2]));
                run3 = fadd2(run3, silu2(a2[pp][3]));
            }
            __syncwarp();
        }
        if (cur_cell >= 0) {
            float* gp = gbase + (size_t)cur_cell * D2;
            float2 v0 = un2(run0), v1 = un2(run1);
            float2 v2 = un2(run2), v3 = un2(run3);
            atomicAdd(gp + 4 * l,           v0.x);
            atomicAdd(gp + 4 * l + 1,       v0.y);
            atomicAdd(gp + 4 * l + 2,       v1.x);
            atomicAdd(gp + 4 * l + 3,       v1.y);
            atomicAdd(gp + 128 + 4 * l,     v2.x);
            atomicAdd(gp + 128 + 4 * l + 1, v2.y);
            atomicAdd(gp + 128 + 4 * l + 2, v3.x);
            atomicAdd(gp + 128 + 4 * l + 3, v3.y);
        }
    }

    // All warps done with W2s/h1s; REDs ordered before subsequent loads.
    __syncthreads();

    // ================= PHASE B: out = Hsum @ W3 + cnt*b3 =================
    float* w3a  = (float*)(smem + S_W3A);
    float* w3b  = (float*)(smem + S_W3B);
    float* Hst  = (float*)(smem + S_HST);
    float* b3s  = (float*)(smem + S_B3);

    const unsigned sa = smem_u32(w3a);
    const unsigned sbuf[2] = { sa, sa + 65536u };

    // prefetch W3 tile 0 (32 rows * 512 f = 4096 float4)
    {
        const char* g0 = (const char*)W3;
        #pragma unroll
        for (int j = 0; j < 8; j++) {
            int f4 = tid + j * 512;
            cpa16(sbuf[0] + f4 * 16, g0 + (size_t)f4 * 16);
        }
        asm volatile("cp.async.commit_group;");
    }

    // stage transposed H via L1-bypassing loads (atomics wrote L2; L1 stale)
    {
        #pragma unroll
        for (int base = tid; base < CELLS * D2; base += 512) {
            int cell = base >> 8;
            int k    = base & 255;
            Hst[k * 65 + cell] = __ldcg(gbase + base);
        }
        b3s[tid] = b3[tid];
    }

    u64 acc[2][16];
    #pragma unroll
    for (int h = 0; h < 2; h++)
        #pragma unroll
        for (int j = 0; j < 16; j++) acc[h][j] = 0ull;

    #pragma unroll 1
    for (int kt = 0; kt < 8; kt++) {
        if (kt < 7) {
            const char* gn = (const char*)(W3 + (size_t)(kt + 1) * 32 * D3);
            #pragma unroll
            for (int j = 0; j < 8; j++) {
                int f4 = tid + j * 512;
                cpa16(sbuf[(kt + 1) & 1] + f4 * 16, gn + (size_t)f4 * 16);
            }
            asm volatile("cp.async.commit_group;");
            asm volatile("cp.async.wait_group 1;");
        } else {
            asm volatile("cp.async.wait_group 0;");
        }
        __syncthreads();

        const float* wt = (kt & 1) ? w3b : w3a;
        #pragma unroll 2
        for (int kk = 0; kk < 32; kk++) {
            const int k = kt * 32 + kk;
            u64 hd0 = dup2(Hst[k * 65 + l]);
            u64 hd1 = dup2(Hst[k * 65 + l + 32]);
            const float* wr = wt + kk * D3 + 32 * w;
            #pragma unroll
            for (int j2 = 0; j2 < 8; j2++) {   // broadcast LDS.128
                ulonglong2 wv = *(const ulonglong2*)(wr + 4 * j2);
                acc[0][2 * j2]     = ffma2(hd0, wv.x, acc[0][2 * j2]);
                acc[0][2 * j2 + 1] = ffma2(hd0, wv.y, acc[0][2 * j2 + 1]);
                acc[1][2 * j2]     = ffma2(hd1, wv.x, acc[1][2 * j2]);
                acc[1][2 * j2 + 1] = ffma2(hd1, wv.y, acc[1][2 * j2 + 1]);
            }
        }
        __syncthreads();   // protect buffer before next prefetch overwrites
    }

    const float c0 = (float)cntsm[l];
    const float c1 = (float)cntsm[l + 32];
    float* outp = out + ((size_t)(bv * 1024 + side * 512)) * 64;
    #pragma unroll
    for (int j = 0; j < 16; j++) {
        int col = 32 * w + 2 * j;
        float bx = b3s[col], by = b3s[col + 1];
        float2 v0 = un2(acc[0][j]);
        float2 v1 = un2(acc[1][j]);
        outp[(size_t)col       * 64 + l]      = v0.x + c0 * bx;
        outp[(size_t)(col + 1) * 64 + l]      = v0.y + c0 * by;
        outp[(size_t)col       * 64 + l + 32] = v1.x + c1 * bx;
        outp[(size_t)(col + 1) * 64 + l + 32] = v1.y + c1 * by;
    }
}

extern "C" void kernel_launch(void* const* d_in, const int* in_sizes, int n_in,
                              void* d_out, int out_size)
{
    const float* ds = (const float*)d_in[0];
    const float* de = (const float*)d_in[1];
    const float* W1 = (const float*)d_in[2];
    const float* b1 = (const float*)d_in[3];
    const float* W2 = (const float*)d_in[4];
    const float* b2 = (const float*)d_in[5];
    const float* W3 = (const float*)d_in[6];
    const float* b3 = (const float*)d_in[7];
    float* out = (float*)d_out;

    cudaFuncSetAttribute(fused_dragnet, cudaFuncAttributeMaxDynamicSharedMemorySize, SMEM_TOT);
    fused_dragnet<<<SBCNT, 512, SMEM_TOT>>>(ds, de, W1, b1, W2, b2, W3, b3, out);
}

// round 9
// speedup vs baseline: 1.0861x; 1.0270x over previous
#include <cuda_runtime.h>
#include <math.h>

#define NPTS  1024
#define D2    256
#define D3    512
#define CELLS 64
#define SBCNT 128

__device__ float g_hsum[SBCNT * CELLS * D2];
__device__ int   g_cnt [SBCNT * CELLS];

__constant__ float c_freq[8] = {
    1.0f, 1.7782794100389228f, 3.1622776601683795f, 5.623413251903491f,
    10.0f, 17.782794100389228f, 31.622776601683793f, 56.23413251903491f
};

typedef unsigned long long u64;

__device__ __forceinline__ u64 pk2(float lo, float hi) {
    u64 r; asm("mov.b64 %0,{%1,%2};" : "=l"(r) : "f"(lo), "f"(hi)); return r;
}
__device__ __forceinline__ u64 dup2(float v) { return pk2(v, v); }
__device__ __forceinline__ u64 ffma2(u64 a, u64 b, u64 c) {
    u64 d; asm("fma.rn.f32x2 %0,%1,%2,%3;" : "=l"(d) : "l"(a), "l"(b), "l"(c)); return d;
}
__device__ __forceinline__ u64 fadd2(u64 a, u64 b) {
    u64 d; asm("add.rn.f32x2 %0,%1,%2;" : "=l"(d) : "l"(a), "l"(b)); return d;
}
__device__ __forceinline__ float2 un2(u64 v) {
    float2 f; asm("mov.b64 {%0,%1},%2;" : "=f"(f.x), "=f"(f.y) : "l"(v)); return f;
}
// silu via 1 MUFU: x*sigmoid(x) = 0.5x*(1+tanh(0.5x))
__device__ __forceinline__ float silu_f(float v) {
    float h = 0.5f * v;
    float t; asm("tanh.approx.f32 %0, %1;" : "=f"(t) : "f"(h));
    return __fmaf_rn(h, t, h);
}
__device__ __forceinline__ u64 silu2(u64 a) {
    float2 v = un2(a); return pk2(silu_f(v.x), silu_f(v.y));
}
// Cody-Waite mod-2pi then MUFU trig (arg reduced to [-pi,pi])
__device__ __forceinline__ float trig_red(float arg, int use_cos) {
    const float INV2PI = 0.15915494309189535f;
    const float C_HI   = 6.2831854820251465f;
    const float C_LO   = -1.7484556e-7f;
    float q = rintf(arg * INV2PI);
    float r = __fmaf_rn(-q, C_HI, arg);
    r = __fmaf_rn(-q, C_LO, r);
    return use_cos ? __cosf(r) : __sinf(r);
}

__device__ __forceinline__ unsigned smem_u32(const void* p) {
    return (unsigned)__cvta_generic_to_shared(p);
}
__device__ __forceinline__ void cpa16(unsigned s, const void* g) {
    asm volatile("cp.async.cg.shared.global [%0], [%1], 16;" :: "r"(s), "l"(g));
}

// ---------------- K1 smem layout (bytes) ----------------
#define S1_W2    0          // 131072
#define S1_W1    131072     // 16384
#define S1_H1    147456     // 65536  (16 warps * 8 pts * 128 f)
#define S1_ORD   212992     // 2048   (u16[1024])
#define S1_CNT   215040     // 256
#define S1_START 215296     // 272
#define S1_CUR   215568     // 256
#define SMEM1    215824

__global__ __launch_bounds__(512, 1)
void k1_embed_agg(const float* __restrict__ ds, const float* __restrict__ de,
                  const float* __restrict__ W1, const float* __restrict__ b1,
                  const float* __restrict__ W2, const float* __restrict__ b2)
{
    extern __shared__ char smem[];
    float*          W2s    = (float*)(smem + S1_W2);
    float*          W1s    = (float*)(smem + S1_W1);
    float*          h1s    = (float*)(smem + S1_H1);
    unsigned short* ordsm  = (unsigned short*)(smem + S1_ORD);
    unsigned*       cntsm  = (unsigned*)(smem + S1_CNT);
    unsigned*       startsm= (unsigned*)(smem + S1_START);
    unsigned*       cursm  = (unsigned*)(smem + S1_CUR);

    const int tid = threadIdx.x;
    const int w   = tid >> 5;
    const int l   = tid & 31;
    const int sb  = blockIdx.x;
    const int side = sb >> 6;
    const int bv   = sb & 63;
    const float* __restrict__ drags = (side ? de : ds) + (size_t)bv * NPTS * 2;
    float* gbase = g_hsum + (size_t)sb * CELLS * D2;

    // stage W2, W1; zero counters; zero this block's g_hsum slice
    {
        const float4* src2 = (const float4*)W2;
        float4* dst2 = (float4*)W2s;
        #pragma unroll 4
        for (int i = tid; i < (128 * 256) / 4; i += 512) dst2[i] = src2[i];
        const float4* src1 = (const float4*)W1;
        float4* dst1 = (float4*)W1s;
        #pragma unroll
        for (int i = tid; i < (32 * 128) / 4; i += 512) dst1[i] = src1[i];
        float4* gz = (float4*)gbase;
        #pragma unroll
        for (int i = tid; i < (CELLS * D2) / 4; i += 512)
            gz[i] = make_float4(0.f, 0.f, 0.f, 0.f);
        if (tid < 64) cntsm[tid] = 0u;
    }
    __syncthreads();

    // counting sort: pass 1
    #pragma unroll
    for (int i = tid; i < NPTS; i += 512) {
        float2 xy = *(const float2*)(drags + 2 * i);
        unsigned cell = (unsigned)((((int)xy.x) >> 6) * 8 + (((int)xy.y) >> 6));
        atomicAdd(&cntsm[cell], 1u);
    }
    __syncthreads();
    if (tid == 0) {
        unsigned run = 0;
        for (int c = 0; c < CELLS; c++) { startsm[c] = run; run += cntsm[c]; }
        startsm[CELLS] = run;
    }
    __syncthreads();
    if (tid < 64) {
        cursm[tid] = startsm[tid];
        g_cnt[sb * CELLS + tid] = (int)cntsm[tid];
    }
    __syncthreads();
    // pass 2: scatter to sorted order
    #pragma unroll
    for (int i = tid; i < NPTS; i += 512) {
        float2 xy = *(const float2*)(drags + 2 * i);
        unsigned cell = (unsigned)((((int)xy.x) >> 6) * 8 + (((int)xy.y) >> 6));
        unsigned pos = atomicAdd(&cursm[cell], 1u);
        ordsm[pos] = (unsigned short)i;
    }
    __syncthreads();

    // per-lane bias registers: lane owns cols [4l,4l+4) and [128+4l,128+4l+4)
    u64 b1r0 = *(const u64*)(b1 + 4 * l);
    u64 b1r1 = *(const u64*)(b1 + 4 * l + 2);
    u64 b2r[4];
    b2r[0] = *(const u64*)(b2 + 4 * l);
    b2r[1] = *(const u64*)(b2 + 4 * l + 2);
    b2r[2] = *(const u64*)(b2 + 128 + 4 * l);
    b2r[3] = *(const u64*)(b2 + 128 + 4 * l + 2);

    // perfectly balanced: warp w processes sorted points [64w, 64w+64)
    float* myh1 = h1s + w * 1024;

    const float fr      = c_freq[l >> 2];
    const int   use_y   = l & 1;
    const int   use_cos = (l >> 1) & 1;

    u64 run0 = 0, run1 = 0, run2 = 0, run3 = 0;
    int cur_cell = -1;

    #pragma unroll 1
    for (int p0 = 64 * w; p0 < 64 * w + 64; p0 += 8) {
        float fv[8]; int cel[8];
        #pragma unroll
        for (int pp = 0; pp < 8; pp++) {
            int idx = (int)ordsm[p0 + pp];
            float2 xy = *(const float2*)(drags + 2 * idx);
            cel[pp] = (((int)xy.x) >> 6) * 8 + (((int)xy.y) >> 6);
            fv[pp] = trig_red((use_y ? xy.y : xy.x) * fr, use_cos);
        }

        // ---- L1: lane owns cols [4l, 4l+4) ----
        u64 a1[8][2];
        #pragma unroll
        for (int pp = 0; pp < 8; pp++) { a1[pp][0] = b1r0; a1[pp][1] = b1r1; }
        #pragma unroll 4
        for (int k = 0; k < 32; k++) {
            ulonglong2 wv = *(const ulonglong2*)(W1s + k * 128 + 4 * l);
            #pragma unroll
            for (int pp = 0; pp < 8; pp++) {
                u64 f2 = dup2(__shfl_sync(0xffffffffu, fv[pp], k));
                a1[pp][0] = ffma2(f2, wv.x, a1[pp][0]);
                a1[pp][1] = ffma2(f2, wv.y, a1[pp][1]);
            }
        }
        #pragma unroll
        for (int pp = 0; pp < 8; pp++) {
            float2 v0 = un2(a1[pp][0]), v1 = un2(a1[pp][1]);
            float4 hv = make_float4(silu_f(v0.x), silu_f(v0.y),
                                    silu_f(v1.x), silu_f(v1.y));
            *(float4*)(myh1 + pp * 128 + 4 * l) = hv;
        }
        __syncwarp();

        // ---- L2: lane owns cols [4l,4l+4) and [128+4l,128+4l+4) ----
        u64 a2[8][4];
        #pragma unroll
        for (int pp = 0; pp < 8; pp++) {
            a2[pp][0] = b2r[0]; a2[pp][1] = b2r[1];
            a2[pp][2] = b2r[2]; a2[pp][3] = b2r[3];
        }
        #pragma unroll 2
        for (int kp = 0; kp < 64; kp++) {
            float2 hp[8];
            #pragma unroll
            for (int pp = 0; pp < 8; pp++)     // broadcast LDS.64
                hp[pp] = *(const float2*)(myh1 + pp * 128 + 2 * kp);
            #pragma unroll
            for (int s = 0; s < 2; s++) {
                const float* wr = W2s + (2 * kp + s) * 256;
                ulonglong2 wA = *(const ulonglong2*)(wr + 4 * l);
                ulonglong2 wB = *(const ulonglong2*)(wr + 128 + 4 * l);
                #pragma unroll
                for (int pp = 0; pp < 8; pp++) {
                    u64 hd = dup2(s ? hp[pp].y : hp[pp].x);
                    a2[pp][0] = ffma2(hd, wA.x, a2[pp][0]);
                    a2[pp][1] = ffma2(hd, wA.y, a2[pp][1]);
                    a2[pp][2] = ffma2(hd, wB.x, a2[pp][2]);
                    a2[pp][3] = ffma2(hd, wB.y, a2[pp][3]);
                }
            }
        }

        // ---- silu + run-accumulate; flush via RED (cross-warp cells safe) ----
        #pragma unroll
        for (int pp = 0; pp < 8; pp++) {
            if (cel[pp] != cur_cell) {
                if (cur_cell >= 0) {
                    float* gp = gbase + (size_t)cur_cell * D2;
                    float2 v0 = un2(run0), v1 = un2(run1);
                    float2 v2 = un2(run2), v3 = un2(run3);
                    atomicAdd(gp + 4 * l,           v0.x);
                    atomicAdd(gp + 4 * l + 1,       v0.y);
                    atomicAdd(gp + 4 * l + 2,       v1.x);
                    atomicAdd(gp + 4 * l + 3,       v1.y);
                    atomicAdd(gp + 128 + 4 * l,     v2.x);
                    atomicAdd(gp + 128 + 4 * l + 1, v2.y);
                    atomicAdd(gp + 128 + 4 * l + 2, v3.x);
                    atomicAdd(gp + 128 + 4 * l + 3, v3.y);
                }
                cur_cell = cel[pp];
                run0 = run1 = run2 = run3 = 0;
            }
            run0 = fadd2(run0, silu2(a2[pp][0]));
            run1 = fadd2(run1, silu2(a2[pp][1]));
            run2 = fadd2(run2, silu2(a2[pp][2]));
            run3 = fadd2(run3, silu2(a2[pp][3]));
        }
        __syncwarp();
    }
    if (cur_cell >= 0) {
        float* gp = gbase + (size_t)cur_cell * D2;
        float2 v0 = un2(run0), v1 = un2(run1);
        float2 v2 = un2(run2), v3 = un2(run3);
        atomicAdd(gp + 4 * l,           v0.x);
        atomicAdd(gp + 4 * l + 1,       v0.y);
        atomicAdd(gp + 4 * l + 2,       v1.x);
        atomicAdd(gp + 4 * l + 3,       v1.y);
        atomicAdd(gp + 128 + 4 * l,     v2.x);
        atomicAdd(gp + 128 + 4 * l + 1, v2.y);
        atomicAdd(gp + 128 + 4 * l + 2, v3.x);
        atomicAdd(gp + 128 + 4 * l + 3, v3.y);
    }
}

// ---------------- K2 smem layout ----------------
#define S2_W3A 0        // 65536 (32 rows * 512 f)
#define S2_W3B 65536    // 65536
#define S2_HST 131072   // 66560 (256 * 65 f, padded transpose)
#define S2_B3  197632   // 2048
#define S2_CNT 199680   // 256
#define SMEM2  199936

// out = Hsum @ W3 + cnt*b3. Warp w owns cols [32w,32w+32); lane l owns
// cells l, l+32. W3 double-buffered via cp.async (8 tiles of 32 rows).
__global__ __launch_bounds__(512, 1)
void k2_l3(const float* __restrict__ W3, const float* __restrict__ b3,
           float* __restrict__ out)
{
    extern __shared__ char smem[];
    float* w3a  = (float*)(smem + S2_W3A);
    float* w3b  = (float*)(smem + S2_W3B);
    float* Hst  = (float*)(smem + S2_HST);
    float* b3s  = (float*)(smem + S2_B3);
    float* cnts = (float*)(smem + S2_CNT);

    const int tid = threadIdx.x;
    const int w   = tid >> 5;
    const int l   = tid & 31;
    const int sb  = blockIdx.x;
    const int side = sb >> 6;
    const int bv   = sb & 63;

    const unsigned sa = smem_u32(w3a);
    const unsigned sbuf[2] = { sa, sa + 65536u };

    // prefetch tile 0
    {
        const char* g0 = (const char*)W3;
        #pragma unroll
        for (int j = 0; j < 8; j++) {
            int f4 = tid + j * 512;
            cpa16(sbuf[0] + f4 * 16, g0 + (size_t)f4 * 16);
        }
        asm volatile("cp.async.commit_group;");
    }

    // stage transposed H: Hst[k*65 + cell] = g_hsum[sb][cell][k]
    {
        const float* src = g_hsum + (size_t)sb * CELLS * D2;
        for (int base = tid; base < CELLS * D2; base += 512) {
            int cell = base >> 8;
            int k    = base & 255;
            Hst[k * 65 + cell] = src[base];
        }
        b3s[tid] = b3[tid];
        if (tid < 64) cnts[tid] = (float)g_cnt[sb * CELLS + tid];
    }

    u64 acc[2][16];
    #pragma unroll
    for (int h = 0; h < 2; h++)
        #pragma unroll
        for (int j = 0; j < 16; j++) acc[h][j] = 0ull;

    #pragma unroll 1
    for (int kt = 0; kt < 8; kt++) {
        if (kt < 7) {   // prefetch next tile into other buffer
            const char* gn = (const char*)(W3 + (size_t)(kt + 1) * 32 * D3);
            #pragma unroll
            for (int j = 0; j < 8; j++) {
                int f4 = tid + j * 512;
                cpa16(sbuf[(kt + 1) & 1] + f4 * 16, gn + (size_t)f4 * 16);
            }
            asm volatile("cp.async.commit_group;");
            asm volatile("cp.async.wait_group 1;");
        } else {
            asm volatile("cp.async.wait_group 0;");
        }
        __syncthreads();

        const float* wt = (kt & 1) ? w3b : w3a;
        #pragma unroll 2
        for (int kk = 0; kk < 32; kk++) {
            const int k = kt * 32 + kk;
            u64 hd0 = dup2(Hst[k * 65 + l]);
            u64 hd1 = dup2(Hst[k * 65 + l + 32]);
            const float* wr = wt + kk * D3 + 32 * w;
            #pragma unroll
            for (int j2 = 0; j2 < 8; j2++) {   // broadcast LDS.128
                ulonglong2 wv = *(const ulonglong2*)(wr + 4 * j2);
                acc[0][2 * j2]     = ffma2(hd0, wv.x, acc[0][2 * j2]);
                acc[0][2 * j2 + 1] = ffma2(hd0, wv.y, acc[0][2 * j2 + 1]);
                acc[1][2 * j2]     = ffma2(hd1, wv.x, acc[1][2 * j2]);
                acc[1][2 * j2 + 1] = ffma2(hd1, wv.y, acc[1][2 * j2 + 1]);
            }
        }
        __syncthreads();   // protect buffer before next prefetch overwrites
    }

    const float c0 = cnts[l], c1 = cnts[l + 32];
    float* outp = out + ((size_t)(bv * 1024 + side * 512)) * 64;
    #pragma unroll
    for (int j = 0; j < 16; j++) {
        int col = 32 * w + 2 * j;
        float bx = b3s[col], by = b3s[col + 1];
        float2 v0 = un2(acc[0][j]);
        float2 v1 = un2(acc[1][j]);
        outp[(size_t)col       * 64 + l]      = v0.x + c0 * bx;
        outp[(size_t)(col + 1) * 64 + l]      = v0.y + c0 * by;
        outp[(size_t)col       * 64 + l + 32] = v1.x + c1 * bx;
        outp[(size_t)(col + 1) * 64 + l + 32] = v1.y + c1 * by;
    }
}

extern "C" void kernel_launch(void* const* d_in, const int* in_sizes, int n_in,
                              void* d_out, int out_size)
{
    const float* ds = (const float*)d_in[0];
    const float* de = (const float*)d_in[1];
    const float* W1 = (const float*)d_in[2];
    const float* b1 = (const float*)d_in[3];
    const float* W2 = (const float*)d_in[4];
    const float* b2 = (const float*)d_in[5];
    const float* W3 = (const float*)d_in[6];
    const float* b3 = (const float*)d_in[7];
    float* out = (float*)d_out;

    cudaFuncSetAttribute(k1_embed_agg, cudaFuncAttributeMaxDynamicSharedMemorySize, SMEM1);
    cudaFuncSetAttribute(k2_l3,        cudaFuncAttributeMaxDynamicSharedMemorySize, SMEM2);

    k1_embed_agg<<<SBCNT, 512, SMEM1>>>(ds, de, W1, b1, W2, b2);
    k2_l3<<<SBCNT, 512, SMEM2>>>(W3, b3, out);
}

// round 11
// speedup vs baseline: 1.1169x; 1.0284x over previous
#include <cuda_runtime.h>
#include <math.h>

#define NPTS  1024
#define D2    256
#define D3    512
#define CELLS 64
#define SBCNT 128

__device__ float g_hsum[SBCNT * CELLS * D2];
__device__ int   g_cnt [SBCNT * CELLS];

__constant__ float c_freq[8] = {
    1.0f, 1.7782794100389228f, 3.1622776601683795f, 5.623413251903491f,
    10.0f, 17.782794100389228f, 31.622776601683793f, 56.23413251903491f
};

typedef unsigned long long u64;

__device__ __forceinline__ u64 pk2(float lo, float hi) {
    u64 r; asm("mov.b64 %0,{%1,%2};" : "=l"(r) : "f"(lo), "f"(hi)); return r;
}
__device__ __forceinline__ u64 dup2(float v) { return pk2(v, v); }
__device__ __forceinline__ u64 ffma2(u64 a, u64 b, u64 c) {
    u64 d; asm("fma.rn.f32x2 %0,%1,%2,%3;" : "=l"(d) : "l"(a), "l"(b), "l"(c)); return d;
}
__device__ __forceinline__ u64 fadd2(u64 a, u64 b) {
    u64 d; asm("add.rn.f32x2 %0,%1,%2;" : "=l"(d) : "l"(a), "l"(b)); return d;
}
__device__ __forceinline__ float2 un2(u64 v) {
    float2 f; asm("mov.b64 {%0,%1},%2;" : "=f"(f.x), "=f"(f.y) : "l"(v)); return f;
}
// silu via 1 MUFU: x*sigmoid(x) = 0.5x*(1+tanh(0.5x))
__device__ __forceinline__ float silu_f(float v) {
    float h = 0.5f * v;
    float t; asm("tanh.approx.f32 %0, %1;" : "=f"(t) : "f"(h));
    return __fmaf_rn(h, t, h);
}
__device__ __forceinline__ u64 silu2(u64 a) {
    float2 v = un2(a); return pk2(silu_f(v.x), silu_f(v.y));
}
// Cody-Waite mod-2pi then MUFU trig (arg reduced to [-pi,pi])
__device__ __forceinline__ float trig_red(float arg, int use_cos) {
    const float INV2PI = 0.15915494309189535f;
    const float C_HI   = 6.2831854820251465f;
    const float C_LO   = -1.7484556e-7f;
    float q = rintf(arg * INV2PI);
    float r = __fmaf_rn(-q, C_HI, arg);
    r = __fmaf_rn(-q, C_LO, r);
    return use_cos ? __cosf(r) : __sinf(r);
}

__device__ __forceinline__ unsigned smem_u32(const void* p) {
    return (unsigned)__cvta_generic_to_shared(p);
}
__device__ __forceinline__ void cpa16(unsigned s, const void* g) {
    asm volatile("cp.async.cg.shared.global [%0], [%1], 16;" :: "r"(s), "l"(g));
}

// ---------------- K1 smem layout (bytes) ----------------
#define S1_W2    0          // 131072
#define S1_W1    131072     // 16384
#define S1_H1    147456     // 65536  (16 warps * 8 pts * 128 f; first 1KB/warp aliases fts)
#define S1_ORD   212992     // 2048   (u16[1024])
#define S1_CNT   215040     // 256
#define S1_START 215296     // 272
#define S1_CUR   215568     // 256
#define SMEM1    215824

__global__ __launch_bounds__(512, 1)
void k1_embed_agg(const float* __restrict__ ds, const float* __restrict__ de,
                  const float* __restrict__ W1, const float* __restrict__ b1,
                  const float* __restrict__ W2, const float* __restrict__ b2)
{
    extern __shared__ char smem[];
    float*          W2s    = (float*)(smem + S1_W2);
    float*          W1s    = (float*)(smem + S1_W1);
    float*          h1s    = (float*)(smem + S1_H1);
    unsigned short* ordsm  = (unsigned short*)(smem + S1_ORD);
    unsigned*       cntsm  = (unsigned*)(smem + S1_CNT);
    unsigned*       startsm= (unsigned*)(smem + S1_START);
    unsigned*       cursm  = (unsigned*)(smem + S1_CUR);

    const int tid = threadIdx.x;
    const int w   = tid >> 5;
    const int l   = tid & 31;
    const int sb  = blockIdx.x;
    const int side = sb >> 6;
    const int bv   = sb & 63;
    const float* __restrict__ drags = (side ? de : ds) + (size_t)bv * NPTS * 2;
    float* gbase = g_hsum + (size_t)sb * CELLS * D2;

    // stage W2, W1; zero counters; zero this block's g_hsum slice
    {
        const float4* src2 = (const float4*)W2;
        float4* dst2 = (float4*)W2s;
        #pragma unroll 4
        for (int i = tid; i < (128 * 256) / 4; i += 512) dst2[i] = src2[i];
        const float4* src1 = (const float4*)W1;
        float4* dst1 = (float4*)W1s;
        #pragma unroll
        for (int i = tid; i < (32 * 128) / 4; i += 512) dst1[i] = src1[i];
        float4* gz = (float4*)gbase;
        #pragma unroll
        for (int i = tid; i < (CELLS * D2) / 4; i += 512)
            gz[i] = make_float4(0.f, 0.f, 0.f, 0.f);
        if (tid < 64) cntsm[tid] = 0u;
    }
    __syncthreads();

    // counting sort: pass 1
    #pragma unroll
    for (int i = tid; i < NPTS; i += 512) {
        float2 xy = *(const float2*)(drags + 2 * i);
        unsigned cell = (unsigned)((((int)xy.x) >> 6) * 8 + (((int)xy.y) >> 6));
        atomicAdd(&cntsm[cell], 1u);
    }
    __syncthreads();
    if (tid == 0) {
        unsigned run = 0;
        for (int c = 0; c < CELLS; c++) { startsm[c] = run; run += cntsm[c]; }
        startsm[CELLS] = run;
    }
    __syncthreads();
    if (tid < 64) {
        cursm[tid] = startsm[tid];
        g_cnt[sb * CELLS + tid] = (int)cntsm[tid];
    }
    __syncthreads();
    // pass 2: scatter to sorted order
    #pragma unroll
    for (int i = tid; i < NPTS; i += 512) {
        float2 xy = *(const float2*)(drags + 2 * i);
        unsigned cell = (unsigned)((((int)xy.x) >> 6) * 8 + (((int)xy.y) >> 6));
        unsigned pos = atomicAdd(&cursm[cell], 1u);
        ordsm[pos] = (unsigned short)i;
    }
    __syncthreads();

    // per-lane bias registers: lane owns cols [4l,4l+4) and [128+4l,128+4l+4)
    u64 b1r0 = *(const u64*)(b1 + 4 * l);
    u64 b1r1 = *(const u64*)(b1 + 4 * l + 2);
    u64 b2r[4];
    b2r[0] = *(const u64*)(b2 + 4 * l);
    b2r[1] = *(const u64*)(b2 + 4 * l + 2);
    b2r[2] = *(const u64*)(b2 + 128 + 4 * l);
    b2r[3] = *(const u64*)(b2 + 128 + 4 * l + 2);

    // perfectly balanced: warp w processes sorted points [64w, 64w+64)
    float* myh1  = h1s + w * 1024;
    float* myfts = myh1;               // fts aliases first 1KB; dead before h1 stores

    const float fr      = c_freq[l >> 2];
    const int   use_y   = l & 1;
    const int   use_cos = (l >> 1) & 1;

    u64 run0 = 0, run1 = 0, run2 = 0, run3 = 0;
    int cur_cell = -1;

    #pragma unroll 1
    for (int p0 = 64 * w; p0 < 64 * w + 64; p0 += 8) {
        float fv[8]; int cel[8];
        #pragma unroll
        for (int pp = 0; pp < 8; pp++) {
            int idx = (int)ordsm[p0 + pp];
            float2 xy = *(const float2*)(drags + 2 * idx);
            cel[pp] = (((int)xy.x) >> 6) * 8 + (((int)xy.y) >> 6);
            fv[pp] = trig_red((use_y ? xy.y : xy.x) * fr, use_cos);
        }
        // publish feature tile: fts[pp][k]; lane l holds feature l
        #pragma unroll
        for (int pp = 0; pp < 8; pp++) myfts[pp * 32 + l] = fv[pp];
        __syncwarp();

        // ---- L1: lane owns cols [4l, 4l+4); features via broadcast LDS.64 ----
        u64 a1[8][2];
        #pragma unroll
        for (int pp = 0; pp < 8; pp++) { a1[pp][0] = b1r0; a1[pp][1] = b1r1; }
        #pragma unroll 4
        for (int k2 = 0; k2 < 16; k2++) {
            float2 f01[8];
            #pragma unroll
            for (int pp = 0; pp < 8; pp++)         // broadcast LDS.64, feeds 2 k's
                f01[pp] = *(const float2*)(myfts + pp * 32 + 2 * k2);
            #pragma unroll
            for (int s = 0; s < 2; s++) {
                const int k = 2 * k2 + s;
                ulonglong2 wv = *(const ulonglong2*)(W1s + k * 128 + 4 * l);
                #pragma unroll
                for (int pp = 0; pp < 8; pp++) {
                    u64 f2 = dup2(s ? f01[pp].y : f01[pp].x);
                    a1[pp][0] = ffma2(f2, wv.x, a1[pp][0]);
                    a1[pp][1] = ffma2(f2, wv.y, a1[pp][1]);
                }
            }
        }
        __syncwarp();   // all fts reads done before h1 stores overwrite the alias
        #pragma unroll
        for (int pp = 0; pp < 8; pp++) {
            float2 v0 = un2(a1[pp][0]), v1 = un2(a1[pp][1]);
            float4 hv = make_float4(silu_f(v0.x), silu_f(v0.y),
                                    silu_f(v1.x), silu_f(v1.y));
            *(float4*)(myh1 + pp * 128 + 4 * l) = hv;
        }
        __syncwarp();

        // ---- L2: lane owns cols [4l,4l+4) and [128+4l,128+4l+4) ----
        u64 a2[8][4];
        #pragma unroll
        for (int pp = 0; pp < 8; pp++) {
            a2[pp][0] = b2r[0]; a2[pp][1] = b2r[1];
            a2[pp][2] = b2r[2]; a2[pp][3] = b2r[3];
        }
        #pragma unroll 2
        for (int kp = 0; kp < 64; kp++) {
            float2 hp[8];
            #pragma unroll
            for (int pp = 0; pp < 8; pp++)     // broadcast LDS.64
                hp[pp] = *(const float2*)(myh1 + pp * 128 + 2 * kp);
            #pragma unroll
            for (int s = 0; s < 2; s++) {
                const float* wr = W2s + (2 * kp + s) * 256;
                ulonglong2 wA = *(const ulonglong2*)(wr + 4 * l);
                ulonglong2 wB = *(const ulonglong2*)(wr + 128 + 4 * l);
                #pragma unroll
                for (int pp = 0; pp < 8; pp++) {
                    u64 hd = dup2(s ? hp[pp].y : hp[pp].x);
                    a2[pp][0] = ffma2(hd, wA.x, a2[pp][0]);
                    a2[pp][1] = ffma2(hd, wA.y, a2[pp][1]);
                    a2[pp][2] = ffma2(hd, wB.x, a2[pp][2]);
                    a2[pp][3] = ffma2(hd, wB.y, a2[pp][3]);
                }
            }
        }

        // ---- silu + run-accumulate; flush via RED (cross-warp cells safe) ----
        #pragma unroll
        for (int pp = 0; pp < 8; pp++) {
            if (cel[pp] != cur_cell) {
                if (cur_cell >= 0) {
                    float* gp = gbase + (size_t)cur_cell * D2;
                    float2 v0 = un2(run0), v1 = un2(run1);
                    float2 v2 = un2(run2), v3 = un2(run3);
                    atomicAdd(gp + 4 * l,           v0.x);
                    atomicAdd(gp + 4 * l + 1,       v0.y);
                    atomicAdd(gp + 4 * l + 2,       v1.x);
                    atomicAdd(gp + 4 * l + 3,       v1.y);
                    atomicAdd(gp + 128 + 4 * l,     v2.x);
                    atomicAdd(gp + 128 + 4 * l + 1, v2.y);
                    atomicAdd(gp + 128 + 4 * l + 2, v3.x);
                    atomicAdd(gp + 128 + 4 * l + 3, v3.y);
                }
                cur_cell = cel[pp];
                run0 = run1 = run2 = run3 = 0;
            }
            run0 = fadd2(run0, silu2(a2[pp][0]));
            run1 = fadd2(run1, silu2(a2[pp][1]));
            run2 = fadd2(run2, silu2(a2[pp][2]));
            run3 = fadd2(run3, silu2(a2[pp][3]));
        }
        __syncwarp();
    }
    if (cur_cell >= 0) {
        float* gp = gbase + (size_t)cur_cell * D2;
        float2 v0 = un2(run0), v1 = un2(run1);
        float2 v2 = un2(run2), v3 = un2(run3);
        atomicAdd(gp + 4 * l,           v0.x);
        atomicAdd(gp + 4 * l + 1,       v0.y);
        atomicAdd(gp + 4 * l + 2,       v1.x);
        atomicAdd(gp + 4 * l + 3,       v1.y);
        atomicAdd(gp + 128 + 4 * l,     v2.x);
        atomicAdd(gp + 128 + 4 * l + 1, v2.y);
        atomicAdd(gp + 128 + 4 * l + 2, v3.x);
        atomicAdd(gp + 128 + 4 * l + 3, v3.y);
    }
}

// ---------------- K2 smem layout ----------------
#define S2_W3A 0        // 65536 (32 rows * 512 f)
#define S2_W3B 65536    // 65536
#define S2_HST 131072   // 66560 (256 * 65 f, padded transpose)
#define S2_B3  197632   // 2048
#define S2_CNT 199680   // 256
#define SMEM2  199936

// out = Hsum @ W3 + cnt*b3. Warp w owns cols [32w,32w+32); lane l owns
// cells l, l+32. W3 double-buffered via cp.async (8 tiles of 32 rows).
__global__ __launch_bounds__(512, 1)
void k2_l3(const float* __restrict__ W3, const float* __restrict__ b3,
           float* __restrict__ out)
{
    extern __shared__ char smem[];
    float* w3a  = (float*)(smem + S2_W3A);
    float* w3b  = (float*)(smem + S2_W3B);
    float* Hst  = (float*)(smem + S2_HST);
    float* b3s  = (float*)(smem + S2_B3);
    float* cnts = (float*)(smem + S2_CNT);

    const int tid = threadIdx.x;
    const int w   = tid >> 5;
    const int l   = tid & 31;
    const int sb  = blockIdx.x;
    const int side = sb >> 6;
    const int bv   = sb & 63;

    const unsigned sa = smem_u32(w3a);
    const unsigned sbuf[2] = { sa, sa + 65536u };

    // prefetch tile 0
    {
        const char* g0 = (const char*)W3;
        #pragma unroll
        for (int j = 0; j < 8; j++) {
            int f4 = tid + j * 512;
            cpa16(sbuf[0] + f4 * 16, g0 + (size_t)f4 * 16);
        }
        asm volatile("cp.async.commit_group;");
    }

    // stage transposed H: Hst[k*65 + cell] = g_hsum[sb][cell][k]
    {
        const float* src = g_hsum + (size_t)sb * CELLS * D2;
        for (int base = tid; base < CELLS * D2; base += 512) {
            int cell = base >> 8;
            int k    = base & 255;
            Hst[k * 65 + cell] = src[base];
        }
        b3s[tid] = b3[tid];
        if (tid < 64) cnts[tid] = (float)g_cnt[sb * CELLS + tid];
    }

    u64 acc[2][16];
    #pragma unroll
    for (int h = 0; h < 2; h++)
        #pragma unroll
        for (int j = 0; j < 16; j++) acc[h][j] = 0ull;

    #pragma unroll 1
    for (int kt = 0; kt < 8; kt++) {
        if (kt < 7) {   // prefetch next tile into other buffer
            const char* gn = (const char*)(W3 + (size_t)(kt + 1) * 32 * D3);
            #pragma unroll
            for (int j = 0; j < 8; j++) {
                int f4 = tid + j * 512;
                cpa16(sbuf[(kt + 1) & 1] + f4 * 16, gn + (size_t)f4 * 16);
            }
            asm volatile("cp.async.commit_group;");
            asm volatile("cp.async.wait_group 1;");
        } else {
            asm volatile("cp.async.wait_group 0;");
        }
        __syncthreads();

        const float* wt = (kt & 1) ? w3b : w3a;
        #pragma unroll 2
        for (int kk = 0; kk < 32; kk++) {
            const int k = kt * 32 + kk;
            u64 hd0 = dup2(Hst[k * 65 + l]);
            u64 hd1 = dup2(Hst[k * 65 + l + 32]);
            const float* wr = wt + kk * D3 + 32 * w;
            #pragma unroll
            for (int j2 = 0; j2 < 8; j2++) {   // broadcast LDS.128
                ulonglong2 wv = *(const ulonglong2*)(wr + 4 * j2);
                acc[0][2 * j2]     = ffma2(hd0, wv.x, acc[0][2 * j2]);
                acc[0][2 * j2 + 1] = ffma2(hd0, wv.y, acc[0][2 * j2 + 1]);
                acc[1][2 * j2]     = ffma2(hd1, wv.x, acc[1][2 * j2]);
                acc[1][2 * j2 + 1] = ffma2(hd1, wv.y, acc[1][2 * j2 + 1]);
            }
        }
        __syncthreads();   // protect buffer before next prefetch overwrites
    }

    const float c0 = cnts[l], c1 = cnts[l + 32];
    float* outp = out + ((size_t)(bv * 1024 + side * 512)) * 64;
    #pragma unroll
    for (int j = 0; j < 16; j++) {
        int col = 32 * w + 2 * j;
        float bx = b3s[col], by = b3s[col + 1];
        float2 v0 = un2(acc[0][j]);
        float2 v1 = un2(acc[1][j]);
        outp[(size_t)col       * 64 + l]      = v0.x + c0 * bx;
        outp[(size_t)(col + 1) * 64 + l]      = v0.y + c0 * by;
        outp[(size_t)col       * 64 + l + 32] = v1.x + c1 * bx;
        outp[(size_t)(col + 1) * 64 + l + 32] = v1.y + c1 * by;
    }
}

extern "C" void kernel_launch(void* const* d_in, const int* in_sizes, int n_in,
                              void* d_out, int out_size)
{
    const float* ds = (const float*)d_in[0];
    const float* de = (const float*)d_in[1];
    const float* W1 = (const float*)d_in[2];
    const float* b1 = (const float*)d_in[3];
    const float* W2 = (const float*)d_in[4];
    const float* b2 = (const float*)d_in[5];
    const float* W3 = (const float*)d_in[6];
    const float* b3 = (const float*)d_in[7];
    float* out = (float*)d_out;

    cudaFuncSetAttribute(k1_embed_agg, cudaFuncAttributeMaxDynamicSharedMemorySize, SMEM1);
    cudaFuncSetAttribute(k2_l3,        cudaFuncAttributeMaxDynamicSharedMemorySize, SMEM2);

    k1_embed_agg<<<SBCNT, 512, SMEM1>>>(ds, de, W1, b1, W2, b2);
    k2_l3<<<SBCNT, 512, SMEM2>>>(W3, b3, out);
}

// round 12
// speedup vs baseline: 1.1325x; 1.0140x over previous
#include <cuda_runtime.h>
#include <math.h>

#define NPTS  1024
#define D2    256
#define D3    512
#define CELLS 64
#define SBCNT 128

__device__ float g_hsum[SBCNT * CELLS * D2];
__device__ int   g_cnt [SBCNT * CELLS];

__constant__ float c_freq[8] = {
    1.0f, 1.7782794100389228f, 3.1622776601683795f, 5.623413251903491f,
    10.0f, 17.782794100389228f, 31.622776601683793f, 56.23413251903491f
};

typedef unsigned long long u64;

__device__ __forceinline__ u64 pk2(float lo, float hi) {
    u64 r; asm("mov.b64 %0,{%1,%2};" : "=l"(r) : "f"(lo), "f"(hi)); return r;
}
__device__ __forceinline__ u64 dup2(float v) { return pk2(v, v); }
__device__ __forceinline__ u64 ffma2(u64 a, u64 b, u64 c) {
    u64 d; asm("fma.rn.f32x2 %0,%1,%2,%3;" : "=l"(d) : "l"(a), "l"(b), "l"(c)); return d;
}
__device__ __forceinline__ u64 fadd2(u64 a, u64 b) {
    u64 d; asm("add.rn.f32x2 %0,%1,%2;" : "=l"(d) : "l"(a), "l"(b)); return d;
}
__device__ __forceinline__ float2 un2(u64 v) {
    float2 f; asm("mov.b64 {%0,%1},%2;" : "=f"(f.x), "=f"(f.y) : "l"(v)); return f;
}
// silu via 1 MUFU: x*sigmoid(x) = 0.5x*(1+tanh(0.5x))
__device__ __forceinline__ float silu_f(float v) {
    float h = 0.5f * v;
    float t; asm("tanh.approx.f32 %0, %1;" : "=f"(t) : "f"(h));
    return __fmaf_rn(h, t, h);
}
__device__ __forceinline__ u64 silu2(u64 a) {
    float2 v = un2(a); return pk2(silu_f(v.x), silu_f(v.y));
}
// Cody-Waite mod-2pi then MUFU trig (arg reduced to [-pi,pi])
__device__ __forceinline__ float trig_red(float arg, int use_cos) {
    const float INV2PI = 0.15915494309189535f;
    const float C_HI   = 6.2831854820251465f;
    const float C_LO   = -1.7484556e-7f;
    float q = rintf(arg * INV2PI);
    float r = __fmaf_rn(-q, C_HI, arg);
    r = __fmaf_rn(-q, C_LO, r);
    return use_cos ? __cosf(r) : __sinf(r);
}

__device__ __forceinline__ unsigned smem_u32(const void* p) {
    return (unsigned)__cvta_generic_to_shared(p);
}
__device__ __forceinline__ void cpa16(unsigned s, const void* g) {
    asm volatile("cp.async.cg.shared.global [%0], [%1], 16;" :: "r"(s), "l"(g));
}
__device__ __forceinline__ void pair_bar(int id) {
    asm volatile("bar.sync %0, 64;" :: "r"(id) : "memory");
}

// ---------------- K1 smem layout (bytes) ----------------
#define S1_W2    0          // 131072
#define S1_W1    131072     // 16384
#define S1_H1    147456     // 65536  (8 pairs * 16 pts * 128 f; fts aliases)
#define S1_ORD   212992     // 2048   (u16[1024])
#define S1_CSORT 215040     // 1024   (u8[1024], cell of sorted pos)
#define S1_CNT   216064     // 256
#define S1_START 216320     // 272
#define S1_CUR   216592     // 256
#define SMEM1    216848

__global__ __launch_bounds__(512, 1)
void k1_embed_agg(const float* __restrict__ ds, const float* __restrict__ de,
                  const float* __restrict__ W1, const float* __restrict__ b1,
                  const float* __restrict__ W2, const float* __restrict__ b2)
{
    extern __shared__ char smem[];
    float*          W2s    = (float*)(smem + S1_W2);
    float*          W1s    = (float*)(smem + S1_W1);
    float*          h1s    = (float*)(smem + S1_H1);
    unsigned short* ordsm  = (unsigned short*)(smem + S1_ORD);
    unsigned char*  csort  = (unsigned char*)(smem + S1_CSORT);
    unsigned*       cntsm  = (unsigned*)(smem + S1_CNT);
    unsigned*       startsm= (unsigned*)(smem + S1_START);
    unsigned*       cursm  = (unsigned*)(smem + S1_CUR);

    const int tid = threadIdx.x;
    const int w   = tid >> 5;
    const int l   = tid & 31;
    const int sb  = blockIdx.x;
    const int side = sb >> 6;
    const int bv   = sb & 63;
    const float* __restrict__ drags = (side ? de : ds) + (size_t)bv * NPTS * 2;
    float* gbase = g_hsum + (size_t)sb * CELLS * D2;

    // stage W2, W1; zero counters; zero this block's g_hsum slice
    {
        const float4* src2 = (const float4*)W2;
        float4* dst2 = (float4*)W2s;
        #pragma unroll 4
        for (int i = tid; i < (128 * 256) / 4; i += 512) dst2[i] = src2[i];
        const float4* src1 = (const float4*)W1;
        float4* dst1 = (float4*)W1s;
        #pragma unroll
        for (int i = tid; i < (32 * 128) / 4; i += 512) dst1[i] = src1[i];
        float4* gz = (float4*)gbase;
        #pragma unroll
        for (int i = tid; i < (CELLS * D2) / 4; i += 512)
            gz[i] = make_float4(0.f, 0.f, 0.f, 0.f);
        if (tid < 64) cntsm[tid] = 0u;
    }
    __syncthreads();

    // counting sort: pass 1
    #pragma unroll
    for (int i = tid; i < NPTS; i += 512) {
        float2 xy = *(const float2*)(drags + 2 * i);
        unsigned cell = (unsigned)((((int)xy.x) >> 6) * 8 + (((int)xy.y) >> 6));
        atomicAdd(&cntsm[cell], 1u);
    }
    __syncthreads();
    if (tid == 0) {
        unsigned run = 0;
        for (int c = 0; c < CELLS; c++) { startsm[c] = run; run += cntsm[c]; }
        startsm[CELLS] = run;
    }
    __syncthreads();
    if (tid < 64) {
        cursm[tid] = startsm[tid];
        g_cnt[sb * CELLS + tid] = (int)cntsm[tid];
    }
    __syncthreads();
    // pass 2: scatter to sorted order (+ sorted cell array)
    #pragma unroll
    for (int i = tid; i < NPTS; i += 512) {
        float2 xy = *(const float2*)(drags + 2 * i);
        unsigned cell = (unsigned)((((int)xy.x) >> 6) * 8 + (((int)xy.y) >> 6));
        unsigned pos = atomicAdd(&cursm[cell], 1u);
        ordsm[pos] = (unsigned short)i;
        csort[pos] = (unsigned char)cell;
    }
    __syncthreads();

    // ---- pair structure: pair p = warps (2p, 2p+1) handles points [128p,128p+128)
    const int pairid = w >> 1;
    const int half   = w & 1;
    float* htile = h1s + pairid * 2048;        // 16 rows x 128 f
    float* myfts = htile + half * 1024;        // aliases own rows 8h..8h+1 (1KB)

    // L1 bias: lane owns cols [4l, 4l+4)
    u64 b1r0 = *(const u64*)(b1 + 4 * l);
    u64 b1r1 = *(const u64*)(b1 + 4 * l + 2);
    // L2 bias: lane owns cols colbase..colbase+3
    const int colbase = 128 * half + 4 * l;
    u64 b2ra = *(const u64*)(b2 + colbase);
    u64 b2rb = *(const u64*)(b2 + colbase + 2);

    const float fr      = c_freq[l >> 2];
    const int   use_y   = l & 1;
    const int   use_cos = (l >> 1) & 1;
    const int   barid   = 1 + pairid;

    u64 run0 = 0, run1 = 0;
    int cur_cell = -1;

    #pragma unroll 1
    for (int b = 0; b < 8; b++) {
        const int p0 = 128 * pairid + 16 * b;

        // ---- (1) L1 for own 8 points ----
        float fv[8];
        #pragma unroll
        for (int pp = 0; pp < 8; pp++) {
            int idx = (int)ordsm[p0 + 8 * half + pp];
            float2 xy = *(const float2*)(drags + 2 * idx);
            fv[pp] = trig_red((use_y ? xy.y : xy.x) * fr, use_cos);
        }
        #pragma unroll
        for (int pp = 0; pp < 8; pp++) myfts[pp * 32 + l] = fv[pp];
        __syncwarp();

        u64 a1[8][2];
        #pragma unroll
        for (int pp = 0; pp < 8; pp++) { a1[pp][0] = b1r0; a1[pp][1] = b1r1; }
        #pragma unroll 4
        for (int k2 = 0; k2 < 16; k2++) {
            float2 f01[8];
            #pragma unroll
            for (int pp = 0; pp < 8; pp++)
                f01[pp] = *(const float2*)(myfts + pp * 32 + 2 * k2);
            #pragma unroll
            for (int s = 0; s < 2; s++) {
                const int k = 2 * k2 + s;
                ulonglong2 wv = *(const ulonglong2*)(W1s + k * 128 + 4 * l);
                #pragma unroll
                for (int pp = 0; pp < 8; pp++) {
                    u64 f2 = dup2(s ? f01[pp].y : f01[pp].x);
                    a1[pp][0] = ffma2(f2, wv.x, a1[pp][0]);
                    a1[pp][1] = ffma2(f2, wv.y, a1[pp][1]);
                }
            }
        }
        __syncwarp();   // fts reads done before h stores overwrite alias
        #pragma unroll
        for (int pp = 0; pp < 8; pp++) {
            float2 v0 = un2(a1[pp][0]), v1 = un2(a1[pp][1]);
            float4 hv = make_float4(silu_f(v0.x), silu_f(v0.y),
                                    silu_f(v1.x), silu_f(v1.y));
            *(float4*)(htile + (8 * half + pp) * 128 + 4 * l) = hv;
        }
        pair_bar(barid);   // both halves of the 16-pt tile ready

        // ---- (2) L2: this warp handles cols [128h, 128h+128) for 16 pts ----
        u64 acc[16][2];
        #pragma unroll
        for (int pp = 0; pp < 16; pp++) { acc[pp][0] = b2ra; acc[pp][1] = b2rb; }
        #pragma unroll 1
        for (int kq = 0; kq < 32; kq++) {
            const float* wr = W2s + (4 * kq) * 256 + colbase;
            ulonglong2 wv0 = *(const ulonglong2*)(wr);
            ulonglong2 wv1 = *(const ulonglong2*)(wr + 256);
            ulonglong2 wv2 = *(const ulonglong2*)(wr + 512);
            ulonglong2 wv3 = *(const ulonglong2*)(wr + 768);
            const float* hb = htile + 4 * kq;
            #pragma unroll
            for (int pp = 0; pp < 16; pp++) {
                float4 h4 = *(const float4*)(hb + pp * 128);   // broadcast LDS.128
                acc[pp][0] = ffma2(dup2(h4.x), wv0.x, acc[pp][0]);
                acc[pp][1] = ffma2(dup2(h4.x), wv0.y, acc[pp][1]);
                acc[pp][0] = ffma2(dup2(h4.y), wv1.x, acc[pp][0]);
                acc[pp][1] = ffma2(dup2(h4.y), wv1.y, acc[pp][1]);
                acc[pp][0] = ffma2(dup2(h4.z), wv2.x, acc[pp][0]);
                acc[pp][1] = ffma2(dup2(h4.z), wv2.y, acc[pp][1]);
                acc[pp][0] = ffma2(dup2(h4.w), wv3.x, acc[pp][0]);
                acc[pp][1] = ffma2(dup2(h4.w), wv3.y, acc[pp][1]);
            }
        }

        // ---- (3) silu + run-accumulate over 16 sorted points ----
        #pragma unroll
        for (int pp = 0; pp < 16; pp++) {
            int c = (int)csort[p0 + pp];   // broadcast LDS.U8
            if (c != cur_cell) {
                if (cur_cell >= 0) {
                    float* gp = gbase + (size_t)cur_cell * D2 + colbase;
                    float2 v0 = un2(run0), v1 = un2(run1);
                    atomicAdd(gp,     v0.x); atomicAdd(gp + 1, v0.y);
                    atomicAdd(gp + 2, v1.x); atomicAdd(gp + 3, v1.y);
                }
                cur_cell = c;
                run0 = run1 = 0;
            }
            run0 = fadd2(run0, silu2(acc[pp][0]));
            run1 = fadd2(run1, silu2(acc[pp][1]));
        }
        pair_bar(barid);   // L2 reads done before next batch overwrites htile
    }
    if (cur_cell >= 0) {
        float* gp = gbase + (size_t)cur_cell * D2 + colbase;
        float2 v0 = un2(run0), v1 = un2(run1);
        atomicAdd(gp,     v0.x); atomicAdd(gp + 1, v0.y);
        atomicAdd(gp + 2, v1.x); atomicAdd(gp + 3, v1.y);
    }
}

// ---------------- K2 smem layout ----------------
#define S2_W3A 0        // 65536 (32 rows * 512 f)
#define S2_W3B 65536    // 65536
#define S2_HST 131072   // 66560 (256 * 65 f, padded transpose)
#define S2_B3  197632   // 2048
#define S2_CNT 199680   // 256
#define SMEM2  199936

// out = Hsum @ W3 + cnt*b3. Warp w owns cols [32w,32w+32); lane l owns
// cells l, l+32. W3 double-buffered via cp.async (8 tiles of 32 rows).
__global__ __launch_bounds__(512, 1)
void k2_l3(const float* __restrict__ W3, const float* __restrict__ b3,
           float* __restrict__ out)
{
    extern __shared__ char smem[];
    float* w3a  = (float*)(smem + S2_W3A);
    float* w3b  = (float*)(smem + S2_W3B);
    float* Hst  = (float*)(smem + S2_HST);
    float* b3s  = (float*)(smem + S2_B3);
    float* cnts = (float*)(smem + S2_CNT);

    const int tid = threadIdx.x;
    const int w   = tid >> 5;
    const int l   = tid & 31;
    const int sb  = blockIdx.x;
    const int side = sb >> 6;
    const int bv   = sb & 63;

    const unsigned sa = smem_u32(w3a);
    const unsigned sbuf[2] = { sa, sa + 65536u };

    // prefetch tile 0
    {
        const char* g0 = (const char*)W3;
        #pragma unroll
        for (int j = 0; j < 8; j++) {
            int f4 = tid + j * 512;
            cpa16(sbuf[0] + f4 * 16, g0 + (size_t)f4 * 16);
        }
        asm volatile("cp.async.commit_group;");
    }

    // stage transposed H: Hst[k*65 + cell] = g_hsum[sb][cell][k]
    {
        const float* src = g_hsum + (size_t)sb * CELLS * D2;
        for (int base = tid; base < CELLS * D2; base += 512) {
            int cell = base >> 8;
            int k    = base & 255;
            Hst[k * 65 + cell] = src[base];
        }
        b3s[tid] = b3[tid];
        if (tid < 64) cnts[tid] = (float)g_cnt[sb * CELLS + tid];
    }

    u64 acc[2][16];
    #pragma unroll
    for (int h = 0; h < 2; h++)
        #pragma unroll
        for (int j = 0; j < 16; j++) acc[h][j] = 0ull;

    #pragma unroll 1
    for (int kt = 0; kt < 8; kt++) {
        if (kt < 7) {   // prefetch next tile into other buffer
            const char* gn = (const char*)(W3 + (size_t)(kt + 1) * 32 * D3);
            #pragma unroll
            for (int j = 0; j < 8; j++) {
                int f4 = tid + j * 512;
                cpa16(sbuf[(kt + 1) & 1] + f4 * 16, gn + (size_t)f4 * 16);
            }
            asm volatile("cp.async.commit_group;");
            asm volatile("cp.async.wait_group 1;");
        } else {
            asm volatile("cp.async.wait_group 0;");
        }
        __syncthreads();

        const float* wt = (kt & 1) ? w3b : w3a;
        #pragma unroll 2
        for (int kk = 0; kk < 32; kk++) {
            const int k = kt * 32 + kk;
            u64 hd0 = dup2(Hst[k * 65 + l]);
            u64 hd1 = dup2(Hst[k * 65 + l + 32]);
            const float* wr = wt + kk * D3 + 32 * w;
            #pragma unroll
            for (int j2 = 0; j2 < 8; j2++) {   // broadcast LDS.128
                ulonglong2 wv = *(const ulonglong2*)(wr + 4 * j2);
                acc[0][2 * j2]     = ffma2(hd0, wv.x, acc[0][2 * j2]);
                acc[0][2 * j2 + 1] = ffma2(hd0, wv.y, acc[0][2 * j2 + 1]);
                acc[1][2 * j2]     = ffma2(hd1, wv.x, acc[1][2 * j2]);
                acc[1][2 * j2 + 1] = ffma2(hd1, wv.y, acc[1][2 * j2 + 1]);
            }
        }
        __syncthreads();   // protect buffer before next prefetch overwrites
    }

    const float c0 = cnts[l], c1 = cnts[l + 32];
    float* outp = out + ((size_t)(bv * 1024 + side * 512)) * 64;
    #pragma unroll
    for (int j = 0; j < 16; j++) {
        int col = 32 * w + 2 * j;
        float bx = b3s[col], by = b3s[col + 1];
        float2 v0 = un2(acc[0][j]);
        float2 v1 = un2(acc[1][j]);
        outp[(size_t)col       * 64 + l]      = v0.x + c0 * bx;
        outp[(size_t)(col + 1) * 64 + l]      = v0.y + c0 * by;
        outp[(size_t)col       * 64 + l + 32] = v1.x + c1 * bx;
        outp[(size_t)(col + 1) * 64 + l + 32] = v1.y + c1 * by;
    }
}

extern "C" void kernel_launch(void* const* d_in, const int* in_sizes, int n_in,
                              void* d_out, int out_size)
{
    const float* ds = (const float*)d_in[0];
    const float* de = (const float*)d_in[1];
    const float* W1 = (const float*)d_in[2];
    const float* b1 = (const float*)d_in[3];
    const float* W2 = (const float*)d_in[4];
    const float* b2 = (const float*)d_in[5];
    const float* W3 = (const float*)d_in[6];
    const float* b3 = (const float*)d_in[7];
    float* out = (float*)d_out;

    cudaFuncSetAttribute(k1_embed_agg, cudaFuncAttributeMaxDynamicSharedMemorySize, SMEM1);
    cudaFuncSetAttribute(k2_l3,        cudaFuncAttributeMaxDynamicSharedMemorySize, SMEM2);

    k1_embed_agg<<<SBCNT, 512, SMEM1>>>(ds, de, W1, b1, W2, b2);
    k2_l3<<<SBCNT, 512, SMEM2>>>(W3, b3, out);
}